// round 15
// baseline (speedup 1.0000x reference)
#include <cuda_runtime.h>
#include <cuda_bf16.h>
#include <math.h>
#include <stdint.h>

// Problem constants
constexpr int Bb   = 2;
constexpr int Ss   = 1024;
constexpr int Hh   = 4096;
constexpr int NHq  = 32;
constexpr int NKVh = 8;
constexpr int HDd  = 128;
constexpr int MTOK = Bb * Ss;             // 2048
constexpr int QD   = NHq * HDd;           // 4096
constexpr int KVD  = NKVh * HDd;          // 1024

// ---------------- device scratch (static; allocation-free) ----------------
__device__ float          g_q[(size_t)MTOK * QD];
__device__ float          g_k[(size_t)MTOK * KVD];
__device__ float          g_v[(size_t)MTOK * KVD];
__device__ __nv_bfloat16  g_ahi[(size_t)MTOK * Hh];
__device__ __nv_bfloat16  g_alo[(size_t)MTOK * Hh];
__device__ __nv_bfloat16  g_qhi[(size_t)MTOK * QD];
__device__ __nv_bfloat16  g_qlo[(size_t)MTOK * QD];
__device__ __nv_bfloat16  g_khi[(size_t)MTOK * KVD];
__device__ __nv_bfloat16  g_klo[(size_t)MTOK * KVD];
__device__ __nv_bfloat16  g_wq[(size_t)QD  * Hh];
__device__ __nv_bfloat16  g_wk[(size_t)KVD * Hh];
__device__ __nv_bfloat16  g_wv[(size_t)KVD * Hh];
__device__ __nv_bfloat16  g_wo[(size_t)Hh  * QD];
__device__ __nv_bfloat16  g_vhi[(size_t)Bb * NKVh * HDd * Ss];
__device__ __nv_bfloat16  g_vlo[(size_t)Bb * NKVh * HDd * Ss];
__device__ double         g_absum[4];
__device__ float          g_gamma[4];

// ---------------- helpers ----------------
__device__ __forceinline__ uint32_t smem_u32(const void* p) {
    uint32_t a;
    asm("{ .reg .u64 t; cvta.to.shared.u64 t, %1; cvt.u32.u64 %0, t; }" : "=r"(a) : "l"(p));
    return a;
}
__device__ __forceinline__ uint32_t packbf(float a, float b) {
    __nv_bfloat162 t = __floats2bfloat162_rn(a, b);
    return *(uint32_t*)&t;
}
__device__ __forceinline__ void mma16816(float* c, const uint32_t* a, const uint32_t* b) {
    asm volatile(
        "mma.sync.aligned.m16n8k16.row.col.f32.bf16.bf16.f32 "
        "{%0,%1,%2,%3}, {%4,%5,%6,%7}, {%8,%9}, {%0,%1,%2,%3};"
        : "+f"(c[0]), "+f"(c[1]), "+f"(c[2]), "+f"(c[3])
        : "r"(a[0]), "r"(a[1]), "r"(a[2]), "r"(a[3]), "r"(b[0]), "r"(b[1]));
}
#define CP_ASYNC16(dst, src) \
    asm volatile("cp.async.cg.shared.global [%0], [%1], 16;" :: "r"(dst), "l"(src))
#define CP_COMMIT() asm volatile("cp.async.commit_group;" ::: "memory")
#define CP_WAIT1()  asm volatile("cp.async.wait_group 1;" ::: "memory")
#define CP_WAIT0()  asm volatile("cp.async.wait_group 0;" ::: "memory")

constexpr int ST = 40;   // bf16 smem row stride (projection GEMM)

// ---------------- gamma: abs-sum reduction (float4) ----------------
__global__ void init_kernel() {
    if (threadIdx.x < 4) g_absum[threadIdx.x] = 0.0;
}

__global__ void abssum_kernel(const float4* __restrict__ w, size_t n4, int idx) {
    float s = 0.f;
    for (size_t i = (size_t)blockIdx.x * blockDim.x + threadIdx.x; i < n4;
         i += (size_t)gridDim.x * blockDim.x) {
        float4 v = w[i];
        s += fabsf(v.x) + fabsf(v.y) + fabsf(v.z) + fabsf(v.w);
    }
    __shared__ double sh[256];
    sh[threadIdx.x] = (double)s;
    __syncthreads();
    for (int o = 128; o > 0; o >>= 1) {
        if ((int)threadIdx.x < o) sh[threadIdx.x] += sh[threadIdx.x + o];
        __syncthreads();
    }
    if (threadIdx.x == 0) atomicAdd(&g_absum[idx], sh[0]);
}

// ---------------- ternary quantization -> bf16 plane ----------------
__global__ void quantize_kernel(const float4* __restrict__ w,
                                __nv_bfloat162* __restrict__ t, size_t n4, int idx) {
    float gamma = (float)(g_absum[idx] / (double)(n4 * 4)) + 1e-5f;
    if (blockIdx.x == 0 && threadIdx.x == 0) g_gamma[idx] = gamma;
    for (size_t i = (size_t)blockIdx.x * blockDim.x + threadIdx.x; i < n4;
         i += (size_t)gridDim.x * blockDim.x) {
        float4 v = w[i];
        float rx = fminf(1.f, fmaxf(-1.f, rintf(v.x / gamma)));
        float ry = fminf(1.f, fmaxf(-1.f, rintf(v.y / gamma)));
        float rz = fminf(1.f, fmaxf(-1.f, rintf(v.z / gamma)));
        float rw = fminf(1.f, fmaxf(-1.f, rintf(v.w / gamma)));
        t[2 * i]     = __floats2bfloat162_rn(rx, ry);
        t[2 * i + 1] = __floats2bfloat162_rn(rz, rw);
    }
}

// ---------------- fp32 -> (hi,lo) bf16 planes ----------------
__global__ void split2_kernel(const float4* __restrict__ x,
                              __nv_bfloat162* __restrict__ hi,
                              __nv_bfloat162* __restrict__ lo, size_t n4) {
    for (size_t i = (size_t)blockIdx.x * blockDim.x + threadIdx.x; i < n4;
         i += (size_t)gridDim.x * blockDim.x) {
        float4 f = x[i];
        __nv_bfloat162 hxy = __floats2bfloat162_rn(f.x, f.y);
        __nv_bfloat162 hzw = __floats2bfloat162_rn(f.z, f.w);
        hi[2 * i]     = hxy;
        hi[2 * i + 1] = hzw;
        lo[2 * i]     = __floats2bfloat162_rn(f.x - __bfloat162float(hxy.x),
                                              f.y - __bfloat162float(hxy.y));
        lo[2 * i + 1] = __floats2bfloat162_rn(f.z - __bfloat162float(hzw.x),
                                              f.w - __bfloat162float(hzw.y));
    }
}

// ---------------- V -> transposed hi/lo planes: vt[bk][d][s] ----------------
__global__ void vsplit_kernel() {
    size_t idx = (size_t)blockIdx.x * blockDim.x + threadIdx.x;
    if (idx >= (size_t)Bb * NKVh * HDd * Ss) return;
    int s  = (int)(idx & (Ss - 1));
    int d  = (int)((idx >> 10) & 127);
    int bk = (int)(idx >> 17);
    int b  = bk >> 3, kv = bk & 7;
    float v = g_v[((size_t)(b * Ss + s)) * KVD + kv * HDd + d];
    __nv_bfloat16 h = __float2bfloat16_rn(v);
    g_vhi[idx] = h;
    g_vlo[idx] = __float2bfloat16_rn(v - __bfloat162float(h));
}

// ================= cp.async-pipelined projection GEMM (128x128 tile, 2-stage) =================
constexpr int PLANE   = 128 * ST;
constexpr int GM_SMEM = 2 * 3 * PLANE * 2;        // 61440 B

__global__ __launch_bounds__(256) void gemm_mma2(
    const __nv_bfloat16* __restrict__ Ahi, const __nv_bfloat16* __restrict__ Alo,
    const __nv_bfloat16* __restrict__ W, float* __restrict__ C,
    int N, int K, int gidx)
{
    extern __shared__ __align__(16) __nv_bfloat16 sb[];
    const uint32_t ubase = smem_u32(sb);

    const int tid  = threadIdx.x;
    const int wid  = tid >> 5;
    const int lane = tid & 31;
    const int g    = lane >> 2;
    const int t    = lane & 3;
    const int m0   = blockIdx.y * 128;
    const int n0   = blockIdx.x * 128;
    const int wrow = (wid >> 2) * 64;
    const int wcol = (wid & 3) * 32;

    const int r0 = (tid * 2)     >> 2, c0 = ((tid * 2)     & 3) * 8;
    const int r1 = (tid * 2 + 1) >> 2, c1 = ((tid * 2 + 1) & 3) * 8;

    float acc[4][4][4];
#pragma unroll
    for (int i = 0; i < 4; i++)
#pragma unroll
        for (int j = 0; j < 4; j++)
#pragma unroll
            for (int r = 0; r < 4; r++) acc[i][j][r] = 0.f;

    const int iters = K >> 5;

    auto issue = [&](int it, int stg) {
        const int kc = it << 5;
        uint32_t s0 = ubase + (uint32_t)(stg * 3 * PLANE) * 2;
        CP_ASYNC16(s0 + (r0 * ST + c0) * 2,               &Ahi[(size_t)(m0 + r0) * K + kc + c0]);
        CP_ASYNC16(s0 + (r1 * ST + c1) * 2,               &Ahi[(size_t)(m0 + r1) * K + kc + c1]);
        CP_ASYNC16(s0 + (PLANE + r0 * ST + c0) * 2,       &Alo[(size_t)(m0 + r0) * K + kc + c0]);
        CP_ASYNC16(s0 + (PLANE + r1 * ST + c1) * 2,       &Alo[(size_t)(m0 + r1) * K + kc + c1]);
        CP_ASYNC16(s0 + (2 * PLANE + r0 * ST + c0) * 2,   &W[(size_t)(n0 + r0) * K + kc + c0]);
        CP_ASYNC16(s0 + (2 * PLANE + r1 * ST + c1) * 2,   &W[(size_t)(n0 + r1) * K + kc + c1]);
        CP_COMMIT();
    };

    issue(0, 0);
    for (int it = 0; it < iters; ++it) {
        const int stg = it & 1;
        if (it + 1 < iters) { issue(it + 1, stg ^ 1); CP_WAIT1(); }
        else                { CP_WAIT0(); }
        __syncthreads();

        const __nv_bfloat16* sah = sb + stg * 3 * PLANE;
        const __nv_bfloat16* sal = sah + PLANE;
        const __nv_bfloat16* sbw = sah + 2 * PLANE;

#pragma unroll
        for (int kk = 0; kk < 32; kk += 16) {
            uint32_t ah[4][4], al[4][4], bf[4][2];
#pragma unroll
            for (int mt = 0; mt < 4; mt++) {
                int m = wrow + mt * 16 + g;
                ah[mt][0] = *(const uint32_t*)&sah[(m    ) * ST + kk + 2 * t    ];
                ah[mt][1] = *(const uint32_t*)&sah[(m + 8) * ST + kk + 2 * t    ];
                ah[mt][2] = *(const uint32_t*)&sah[(m    ) * ST + kk + 2 * t + 8];
                ah[mt][3] = *(const uint32_t*)&sah[(m + 8) * ST + kk + 2 * t + 8];
                al[mt][0] = *(const uint32_t*)&sal[(m    ) * ST + kk + 2 * t    ];
                al[mt][1] = *(const uint32_t*)&sal[(m + 8) * ST + kk + 2 * t    ];
                al[mt][2] = *(const uint32_t*)&sal[(m    ) * ST + kk + 2 * t + 8];
                al[mt][3] = *(const uint32_t*)&sal[(m + 8) * ST + kk + 2 * t + 8];
            }
#pragma unroll
            for (int nt = 0; nt < 4; nt++) {
                int n = wcol + nt * 8 + g;
                bf[nt][0] = *(const uint32_t*)&sbw[n * ST + kk + 2 * t    ];
                bf[nt][1] = *(const uint32_t*)&sbw[n * ST + kk + 2 * t + 8];
            }
#pragma unroll
            for (int mt = 0; mt < 4; mt++)
#pragma unroll
                for (int nt = 0; nt < 4; nt++) {
                    mma16816(acc[mt][nt], ah[mt], bf[nt]);
                    mma16816(acc[mt][nt], al[mt], bf[nt]);
                }
        }
        __syncthreads();
    }

    const float gamma = g_gamma[gidx];
#pragma unroll
    for (int mt = 0; mt < 4; mt++) {
#pragma unroll
        for (int nt = 0; nt < 4; nt++) {
            int m = m0 + wrow + mt * 16 + g;
            int n = n0 + wcol + nt * 8 + 2 * t;
            float2 lo = make_float2(acc[mt][nt][0] * gamma, acc[mt][nt][1] * gamma);
            float2 hi = make_float2(acc[mt][nt][2] * gamma, acc[mt][nt][3] * gamma);
            *(float2*)&C[(size_t)m * N + n]       = lo;
            *(float2*)&C[(size_t)(m + 8) * N + n] = hi;
        }
    }
}

// ---------------- RoPE -> hi/lo bf16 planes, uses position_ids ----------------
__global__ void rope_plane(const float* __restrict__ x,
                           __nv_bfloat16* __restrict__ hi,
                           __nv_bfloat16* __restrict__ lo,
                           int nheads, const int* __restrict__ pos_ids) {
    size_t idx = (size_t)blockIdx.x * blockDim.x + threadIdx.x;
    size_t total = (size_t)MTOK * nheads * 64;
    if (idx >= total) return;
    int d = (int)(idx & 63);
    size_t th = idx >> 6;
    int head = (int)(th % nheads);
    size_t tok = th / nheads;
    int pos = pos_ids[tok];
    float inv_freq = 1.0f / powf(10000.0f, (float)d * (1.0f / 64.0f));
    float fr = (float)pos * inv_freq;
    float s, c;
    sincosf(fr, &s, &c);
    size_t base = tok * ((size_t)nheads * HDd) + (size_t)head * HDd;
    float x1 = x[base + d], x2 = x[base + d + 64];
    float y1 = x1 * c - x2 * s;
    float y2 = x2 * c + x1 * s;
    __nv_bfloat16 h1 = __float2bfloat16_rn(y1);
    __nv_bfloat16 h2 = __float2bfloat16_rn(y2);
    hi[base + d]      = h1;
    hi[base + d + 64] = h2;
    lo[base + d]      = __float2bfloat16_rn(y1 - __bfloat162float(h1));
    lo[base + d + 64] = __float2bfloat16_rn(y2 - __bfloat162float(h2));
}

// ================= fused flash attention v2 (hoisted Q, K/P buffer sharing) =================
constexpr int PST = 136;
constexpr int FL_SMEM = 210944;

__global__ __launch_bounds__(256) void flash_mma() {
    extern __shared__ char ds[];
    __nv_bfloat16* sQh = (__nv_bfloat16*)(ds);
    __nv_bfloat16* sQl = (__nv_bfloat16*)(ds + 34816);
    __nv_bfloat16* sPh = (__nv_bfloat16*)(ds + 69632);
    __nv_bfloat16* sPl = (__nv_bfloat16*)(ds + 104448);
    __nv_bfloat16* sVh = (__nv_bfloat16*)(ds + 139264);
    __nv_bfloat16* sVl = (__nv_bfloat16*)(ds + 174080);
    float*         red = (float*)        (ds + 208896);

    const int bh = blockIdx.y;
    const int b = bh >> 5, h = bh & 31;
    const int kvh = h >> 2;
    const int bk = b * NKVh + kvh;
    const int m0 = blockIdx.x * 128;

    const __nv_bfloat16* __restrict__ Qh = g_qhi + (size_t)(b * Ss + m0) * QD + h * HDd;
    const __nv_bfloat16* __restrict__ Ql = g_qlo + (size_t)(b * Ss + m0) * QD + h * HDd;
    const __nv_bfloat16* __restrict__ Kh = g_khi + (size_t)b * Ss * KVD + kvh * HDd;
    const __nv_bfloat16* __restrict__ Kl = g_klo + (size_t)b * Ss * KVD + kvh * HDd;
    const __nv_bfloat16* __restrict__ Vh = g_vhi + (size_t)bk * HDd * Ss;
    const __nv_bfloat16* __restrict__ Vl = g_vlo + (size_t)bk * HDd * Ss;
    __nv_bfloat16* __restrict__ Ohi = g_ahi + (size_t)b * Ss * QD + (size_t)h * HDd;
    __nv_bfloat16* __restrict__ Olo = g_alo + (size_t)b * Ss * QD + (size_t)h * HDd;

    const int tid  = threadIdx.x;
    const int wid  = tid >> 5;
    const int lane = tid & 31;
    const int g    = lane >> 2;
    const int t    = lane & 3;
    const int wrow = (wid >> 2) * 64;
    const int wcol = (wid & 3) * 32;
    const int wc   = wid & 3;
    const float scale = 0.08838834764831845f;  // 1/sqrt(128)

    // ---- hoisted Q load (once per block) ----
#pragma unroll
    for (int l = 0; l < 8; l++) {
        int seg = tid + l * 256;
        int row = seg >> 4;
        int cs  = (seg & 15) * 8;
        *(uint4*)&sQh[row * PST + cs] = *(const uint4*)&Qh[(size_t)row * QD + cs];
        *(uint4*)&sQl[row * PST + cs] = *(const uint4*)&Ql[(size_t)row * QD + cs];
    }

    float oacc[4][4][4];
    float M[8], L[8];
#pragma unroll
    for (int i = 0; i < 4; i++)
#pragma unroll
        for (int j = 0; j < 4; j++)
#pragma unroll
            for (int r = 0; r < 4; r++) oacc[i][j][r] = 0.f;
#pragma unroll
    for (int i = 0; i < 8; i++) { M[i] = -INFINITY; L[i] = 0.f; }

    for (int n0 = 0; n0 <= m0; n0 += 128) {
        // ---- load K tile (into P buffer) + V tile ----
#pragma unroll
        for (int l = 0; l < 8; l++) {
            int seg = tid + l * 256;
            int row = seg >> 4;
            int cs  = (seg & 15) * 8;
            *(uint4*)&sPh[row * PST + cs] = *(const uint4*)&Kh[(size_t)(n0 + row) * KVD + cs];
            *(uint4*)&sPl[row * PST + cs] = *(const uint4*)&Kl[(size_t)(n0 + row) * KVD + cs];
            *(uint4*)&sVh[row * PST + cs] = *(const uint4*)&Vh[(size_t)row * Ss + n0 + cs];
            *(uint4*)&sVl[row * PST + cs] = *(const uint4*)&Vl[(size_t)row * Ss + n0 + cs];
        }
        __syncthreads();

        // ---- QK: s = Q . K^T (3-plane) ----
        float s[4][4][4];
#pragma unroll
        for (int i = 0; i < 4; i++)
#pragma unroll
            for (int j = 0; j < 4; j++)
#pragma unroll
                for (int r = 0; r < 4; r++) s[i][j][r] = 0.f;

#pragma unroll
        for (int kk = 0; kk < 128; kk += 16) {
            uint32_t ah[4][4], al[4][4], bh2[4][2], bl2[4][2];
#pragma unroll
            for (int mt = 0; mt < 4; mt++) {
                int m = wrow + mt * 16 + g;
                ah[mt][0] = *(const uint32_t*)&sQh[(m    ) * PST + kk + 2 * t    ];
                ah[mt][1] = *(const uint32_t*)&sQh[(m + 8) * PST + kk + 2 * t    ];
                ah[mt][2] = *(const uint32_t*)&sQh[(m    ) * PST + kk + 2 * t + 8];
                ah[mt][3] = *(const uint32_t*)&sQh[(m + 8) * PST + kk + 2 * t + 8];
                al[mt][0] = *(const uint32_t*)&sQl[(m    ) * PST + kk + 2 * t    ];
                al[mt][1] = *(const uint32_t*)&sQl[(m + 8) * PST + kk + 2 * t    ];
                al[mt][2] = *(const uint32_t*)&sQl[(m    ) * PST + kk + 2 * t + 8];
                al[mt][3] = *(const uint32_t*)&sQl[(m + 8) * PST + kk + 2 * t + 8];
            }
#pragma unroll
            for (int nt = 0; nt < 4; nt++) {
                int n = wcol + nt * 8 + g;
                bh2[nt][0] = *(const uint32_t*)&sPh[n * PST + kk + 2 * t    ];
                bh2[nt][1] = *(const uint32_t*)&sPh[n * PST + kk + 2 * t + 8];
                bl2[nt][0] = *(const uint32_t*)&sPl[n * PST + kk + 2 * t    ];
                bl2[nt][1] = *(const uint32_t*)&sPl[n * PST + kk + 2 * t + 8];
            }
#pragma unroll
            for (int mt = 0; mt < 4; mt++)
#pragma unroll
                for (int nt = 0; nt < 4; nt++) {
                    mma16816(s[mt][nt], ah[mt], bh2[nt]);
                    mma16816(s[mt][nt], al[mt], bh2[nt]);
                    mma16816(s[mt][nt], ah[mt], bl2[nt]);
                }
        }
        __syncthreads();   // all warps done reading K from sP

        // ---- scale + causal mask + tile row-max ----
        float tstat[8];
#pragma unroll
        for (int mt = 0; mt < 4; mt++) {
#pragma unroll
            for (int half = 0; half < 2; half++) {
                int rl = wrow + mt * 16 + g + half * 8;
                float mx = -INFINITY;
#pragma unroll
                for (int nt = 0; nt < 4; nt++) {
#pragma unroll
                    for (int j = 0; j < 2; j++) {
                        int cl = wcol + nt * 8 + 2 * t + j;
                        float sv = s[mt][nt][half * 2 + j] * scale;
                        bool ok = (n0 + cl) <= (m0 + rl);
                        sv = ok ? sv : -INFINITY;
                        s[mt][nt][half * 2 + j] = sv;
                        mx = fmaxf(mx, sv);
                    }
                }
                mx = fmaxf(mx, __shfl_xor_sync(0xffffffffu, mx, 1));
                mx = fmaxf(mx, __shfl_xor_sync(0xffffffffu, mx, 2));
                tstat[mt * 2 + half] = mx;
            }
        }
        if (t == 0) {
#pragma unroll
            for (int mt = 0; mt < 4; mt++)
#pragma unroll
                for (int half = 0; half < 2; half++) {
                    int rl = wrow + mt * 16 + g + half * 8;
                    red[rl * 4 + wc] = tstat[mt * 2 + half];
                }
        }
        __syncthreads();

        float Mn[8], alpha[8];
#pragma unroll
        for (int mt = 0; mt < 4; mt++) {
#pragma unroll
            for (int half = 0; half < 2; half++) {
                int i = mt * 2 + half;
                int rl = wrow + mt * 16 + g + half * 8;
                float tm = fmaxf(fmaxf(red[rl * 4 + 0], red[rl * 4 + 1]),
                                 fmaxf(red[rl * 4 + 2], red[rl * 4 + 3]));
                Mn[i] = fmaxf(M[i], tm);
                alpha[i] = expf(M[i] - Mn[i]);
                M[i] = Mn[i];
            }
        }
        __syncthreads();   // red reused for sums

        // ---- p = exp(s - M) -> P hi/lo into sP (K dead), row sums ----
#pragma unroll
        for (int mt = 0; mt < 4; mt++) {
#pragma unroll
            for (int half = 0; half < 2; half++) {
                int i = mt * 2 + half;
                int rl = wrow + mt * 16 + g + half * 8;
                float sm = 0.f;
#pragma unroll
                for (int nt = 0; nt < 4; nt++) {
                    float pa = expf(s[mt][nt][half * 2 + 0] - M[i]);
                    float pb = expf(s[mt][nt][half * 2 + 1] - M[i]);
                    sm += pa + pb;
                    float ha = __bfloat162float(__float2bfloat16_rn(pa));
                    float hb = __bfloat162float(__float2bfloat16_rn(pb));
                    int cl = wcol + nt * 8 + 2 * t;
                    *(uint32_t*)&sPh[rl * PST + cl] = packbf(ha, hb);
                    *(uint32_t*)&sPl[rl * PST + cl] = packbf(pa - ha, pb - hb);
                }
                sm += __shfl_xor_sync(0xffffffffu, sm, 1);
                sm += __shfl_xor_sync(0xffffffffu, sm, 2);
                tstat[i] = sm;
            }
        }
        if (t == 0) {
#pragma unroll
            for (int mt = 0; mt < 4; mt++)
#pragma unroll
                for (int half = 0; half < 2; half++) {
                    int rl = wrow + mt * 16 + g + half * 8;
                    red[rl * 4 + wc] = tstat[mt * 2 + half];
                }
        }
        __syncthreads();

#pragma unroll
        for (int mt = 0; mt < 4; mt++) {
#pragma unroll
            for (int half = 0; half < 2; half++) {
                int i = mt * 2 + half;
                int rl = wrow + mt * 16 + g + half * 8;
                float rs = red[rl * 4 + 0] + red[rl * 4 + 1] +
                           red[rl * 4 + 2] + red[rl * 4 + 3];
                L[i] = L[i] * alpha[i] + rs;
            }
        }
#pragma unroll
        for (int mt = 0; mt < 4; mt++)
#pragma unroll
            for (int nt = 0; nt < 4; nt++) {
                oacc[mt][nt][0] *= alpha[mt * 2 + 0];
                oacc[mt][nt][1] *= alpha[mt * 2 + 0];
                oacc[mt][nt][2] *= alpha[mt * 2 + 1];
                oacc[mt][nt][3] *= alpha[mt * 2 + 1];
            }

        // ---- PV: O += P . V^T ----
#pragma unroll
        for (int kk = 0; kk < 128; kk += 16) {
            uint32_t ah[4][4], al[4][4], bh2[4][2], bl2[4][2];
#pragma unroll
            for (int mt = 0; mt < 4; mt++) {
                int m = wrow + mt * 16 + g;
                ah[mt][0] = *(const uint32_t*)&sPh[(m    ) * PST + kk + 2 * t    ];
                ah[mt][1] = *(const uint32_t*)&sPh[(m + 8) * PST + kk + 2 * t    ];
                ah[mt][2] = *(const uint32_t*)&sPh[(m    ) * PST + kk + 2 * t + 8];
                ah[mt][3] = *(const uint32_t*)&sPh[(m + 8) * PST + kk + 2 * t + 8];
                al[mt][0] = *(const uint32_t*)&sPl[(m    ) * PST + kk + 2 * t    ];
                al[mt][1] = *(const uint32_t*)&sPl[(m + 8) * PST + kk + 2 * t    ];
                al[mt][2] = *(const uint32_t*)&sPl[(m    ) * PST + kk + 2 * t + 8];
                al[mt][3] = *(const uint32_t*)&sPl[(m + 8) * PST + kk + 2 * t + 8];
            }
#pragma unroll
            for (int nt = 0; nt < 4; nt++) {
                int n = wcol + nt * 8 + g;
                bh2[nt][0] = *(const uint32_t*)&sVh[n * PST + kk + 2 * t    ];
                bh2[nt][1] = *(const uint32_t*)&sVh[n * PST + kk + 2 * t + 8];
                bl2[nt][0] = *(const uint32_t*)&sVl[n * PST + kk + 2 * t    ];
                bl2[nt][1] = *(const uint32_t*)&sVl[n * PST + kk + 2 * t + 8];
            }
#pragma unroll
            for (int mt = 0; mt < 4; mt++)
#pragma unroll
                for (int nt = 0; nt < 4; nt++) {
                    mma16816(oacc[mt][nt], ah[mt], bh2[nt]);
                    mma16816(oacc[mt][nt], al[mt], bh2[nt]);
                    mma16816(oacc[mt][nt], ah[mt], bl2[nt]);
                }
        }
        __syncthreads();
    }

    // ---- epilogue: O /= L, write hi/lo bf16 planes ----
    float inv[8];
#pragma unroll
    for (int i = 0; i < 8; i++) inv[i] = 1.f / L[i];
#pragma unroll
    for (int mt = 0; mt < 4; mt++) {
#pragma unroll
        for (int nt = 0; nt < 4; nt++) {
            int m = m0 + wrow + mt * 16 + g;
            int n = wcol + nt * 8 + 2 * t;
            float v0 = oacc[mt][nt][0] * inv[mt * 2 + 0];
            float v1 = oacc[mt][nt][1] * inv[mt * 2 + 0];
            float h0 = __bfloat162float(__float2bfloat16_rn(v0));
            float h1 = __bfloat162float(__float2bfloat16_rn(v1));
            *(uint32_t*)&Ohi[(size_t)m * QD + n] = packbf(h0, h1);
            *(uint32_t*)&Olo[(size_t)m * QD + n] = packbf(v0 - h0, v1 - h1);

            float v2 = oacc[mt][nt][2] * inv[mt * 2 + 1];
            float v3 = oacc[mt][nt][3] * inv[mt * 2 + 1];
            float h2 = __bfloat162float(__float2bfloat16_rn(v2));
            float h3 = __bfloat162float(__float2bfloat16_rn(v3));
            *(uint32_t*)&Ohi[(size_t)(m + 8) * QD + n] = packbf(h2, h3);
            *(uint32_t*)&Olo[(size_t)(m + 8) * QD + n] = packbf(v2 - h2, v3 - h3);
        }
    }
}

// ---------------- launch ----------------
extern "C" void kernel_launch(void* const* d_in, const int* in_sizes, int n_in,
                              void* d_out, int out_size)
{
    const float* hidden = nullptr;
    const float* big16[2] = {nullptr, nullptr};
    const float* sml4[2]  = {nullptr, nullptr};
    const int*   posid = nullptr;
    int hidden_idx = -1, nb = 0, ns = 0;
    for (int i = 0; i < n_in; i++) {
        if (in_sizes[i] == 8388608)               { hidden = (const float*)d_in[i]; hidden_idx = i; }
        else if (in_sizes[i] == 16777216 && nb<2) { big16[nb++] = (const float*)d_in[i]; }
        else if (in_sizes[i] == 4194304  && ns<2) { sml4[ns++]  = (const float*)d_in[i]; }
        else if (in_sizes[i] == 2048)             { posid = (const int*)d_in[i]; }
    }
    const float* Wq = (hidden_idx == 0) ? big16[0] : big16[1];
    const float* Wo = (hidden_idx == 0) ? big16[1] : big16[0];
    const float* Wk = sml4[0];
    const float* Wv = sml4[1];
    float* out = (float*)d_out;

    void *pq, *pk, *pv, *pahi, *palo, *pqhi, *pqlo, *pkhi, *pklo,
         *pwq, *pwk, *pwv, *pwo;
    cudaGetSymbolAddress(&pq, g_q);
    cudaGetSymbolAddress(&pk, g_k);
    cudaGetSymbolAddress(&pv, g_v);
    cudaGetSymbolAddress(&pahi, g_ahi);
    cudaGetSymbolAddress(&palo, g_alo);
    cudaGetSymbolAddress(&pqhi, g_qhi);
    cudaGetSymbolAddress(&pqlo, g_qlo);
    cudaGetSymbolAddress(&pkhi, g_khi);
    cudaGetSymbolAddress(&pklo, g_klo);
    cudaGetSymbolAddress(&pwq, g_wq);
    cudaGetSymbolAddress(&pwk, g_wk);
    cudaGetSymbolAddress(&pwv, g_wv);
    cudaGetSymbolAddress(&pwo, g_wo);

    cudaFuncSetAttribute(gemm_mma2, cudaFuncAttributeMaxDynamicSharedMemorySize, GM_SMEM);
    cudaFuncSetAttribute(flash_mma, cudaFuncAttributeMaxDynamicSharedMemorySize, FL_SMEM);

    const size_t nQ4 = (size_t)QD * Hh / 4;
    const size_t nK4 = (size_t)KVD * Hh / 4;
    const size_t nO4 = (size_t)Hh * QD / 4;
    const size_t nH4 = (size_t)MTOK * Hh / 4;

    // Streams/events created ONCE (first = correctness call, pre-capture),
    // so no driver pool allocation ever happens during graph capture.
    static cudaStream_t s2 = nullptr, s3 = nullptr;
    static cudaEvent_t ev0, evK, evV, evO, evQ, evKp, evVg, evVS, evRQ, evRK;
    if (s2 == nullptr) {
        cudaStreamCreateWithFlags(&s2, cudaStreamNonBlocking);
        cudaStreamCreateWithFlags(&s3, cudaStreamNonBlocking);
        cudaEventCreateWithFlags(&ev0, cudaEventDisableTiming);
        cudaEventCreateWithFlags(&evK, cudaEventDisableTiming);
        cudaEventCreateWithFlags(&evV, cudaEventDisableTiming);
        cudaEventCreateWithFlags(&evO, cudaEventDisableTiming);
        cudaEventCreateWithFlags(&evQ, cudaEventDisableTiming);
        cudaEventCreateWithFlags(&evKp, cudaEventDisableTiming);
        cudaEventCreateWithFlags(&evVg, cudaEventDisableTiming);
        cudaEventCreateWithFlags(&evVS, cudaEventDisableTiming);
        cudaEventCreateWithFlags(&evRQ, cudaEventDisableTiming);
        cudaEventCreateWithFlags(&evRK, cudaEventDisableTiming);
    }

    init_kernel<<<1, 32>>>();
    cudaEventRecord(ev0, 0);
    cudaStreamWaitEvent(s2, ev0, 0);
    cudaStreamWaitEvent(s3, ev0, 0);

    // s2: K/V/O weight preprocessing (memory-bound, overlaps tensor GEMMs)
    abssum_kernel<<<2048, 256, 0, s2>>>((const float4*)Wk, nK4, 1);
    quantize_kernel<<<4096, 256, 0, s2>>>((const float4*)Wk, (__nv_bfloat162*)pwk, nK4, 1);
    cudaEventRecord(evK, s2);
    abssum_kernel<<<2048, 256, 0, s2>>>((const float4*)Wv, nK4, 2);
    quantize_kernel<<<4096, 256, 0, s2>>>((const float4*)Wv, (__nv_bfloat162*)pwv, nK4, 2);
    cudaEventRecord(evV, s2);
    abssum_kernel<<<2048, 256, 0, s2>>>((const float4*)Wo, nO4, 3);
    quantize_kernel<<<4096, 256, 0, s2>>>((const float4*)Wo, (__nv_bfloat162*)pwo, nO4, 3);
    cudaEventRecord(evO, s2);

    // main stream: Q path
    abssum_kernel<<<2048, 256>>>((const float4*)Wq, nQ4, 0);
    quantize_kernel<<<4096, 256>>>((const float4*)Wq, (__nv_bfloat162*)pwq, nQ4, 0);
    split2_kernel<<<4096, 256>>>((const float4*)hidden, (__nv_bfloat162*)pahi,
                                 (__nv_bfloat162*)palo, nH4);
    gemm_mma2<<<dim3(QD / 128, MTOK / 128), 256, GM_SMEM>>>(
        (const __nv_bfloat16*)pahi, (const __nv_bfloat16*)palo,
        (const __nv_bfloat16*)pwq, (float*)pq, QD, Hh, 0);
    cudaEventRecord(evQ, 0);

    // s3: rope_q overlaps K/V projections
    cudaStreamWaitEvent(s3, evQ, 0);
    rope_plane<<<(int)(((size_t)MTOK * NHq * 64 + 255) / 256), 256, 0, s3>>>(
        (const float*)pq, (__nv_bfloat16*)pqhi, (__nv_bfloat16*)pqlo, NHq, posid);
    cudaEventRecord(evRQ, s3);

    cudaStreamWaitEvent(0, evK, 0);
    gemm_mma2<<<dim3(KVD / 128, MTOK / 128), 256, GM_SMEM>>>(
        (const __nv_bfloat16*)pahi, (const __nv_bfloat16*)palo,
        (const __nv_bfloat16*)pwk, (float*)pk, KVD, Hh, 1);
    cudaEventRecord(evKp, 0);

    // s3: rope_k overlaps V projection
    cudaStreamWaitEvent(s3, evKp, 0);
    rope_plane<<<(int)(((size_t)MTOK * NKVh * 64 + 255) / 256), 256, 0, s3>>>(
        (const float*)pk, (__nv_bfloat16*)pkhi, (__nv_bfloat16*)pklo, NKVh, posid);
    cudaEventRecord(evRK, s3);

    cudaStreamWaitEvent(0, evV, 0);
    gemm_mma2<<<dim3(KVD / 128, MTOK / 128), 256, GM_SMEM>>>(
        (const __nv_bfloat16*)pahi, (const __nv_bfloat16*)palo,
        (const __nv_bfloat16*)pwv, (float*)pv, KVD, Hh, 2);
    cudaEventRecord(evVg, 0);

    // s2: V transpose/split
    cudaStreamWaitEvent(s2, evVg, 0);
    vsplit_kernel<<<(int)(((size_t)Bb * NKVh * HDd * Ss + 255) / 256), 256, 0, s2>>>();
    cudaEventRecord(evVS, s2);

    cudaStreamWaitEvent(0, evRQ, 0);
    cudaStreamWaitEvent(0, evRK, 0);
    cudaStreamWaitEvent(0, evVS, 0);
    flash_mma<<<dim3(Ss / 128, Bb * NHq), 256, FL_SMEM>>>();

    cudaStreamWaitEvent(0, evO, 0);
    gemm_mma2<<<dim3(Hh / 128, MTOK / 128), 256, GM_SMEM>>>(
        (const __nv_bfloat16*)pahi, (const __nv_bfloat16*)palo,
        (const __nv_bfloat16*)pwo, out, Hh, QD, 3);
}

// round 16
// speedup vs baseline: 1.1451x; 1.1451x over previous
#include <cuda_runtime.h>
#include <cuda_bf16.h>
#include <math.h>
#include <stdint.h>

// Problem constants
constexpr int Bb   = 2;
constexpr int Ss   = 1024;
constexpr int Hh   = 4096;
constexpr int NHq  = 32;
constexpr int NKVh = 8;
constexpr int HDd  = 128;
constexpr int MTOK = Bb * Ss;             // 2048
constexpr int QD   = NHq * HDd;           // 4096
constexpr int KVD  = NKVh * HDd;          // 1024

// ---------------- device scratch (static; allocation-free) ----------------
__device__ float          g_q[(size_t)MTOK * QD];
__device__ float          g_k[(size_t)MTOK * KVD];
__device__ float          g_v[(size_t)MTOK * KVD];
__device__ __nv_bfloat16  g_ahi[(size_t)MTOK * Hh];
__device__ __nv_bfloat16  g_alo[(size_t)MTOK * Hh];
__device__ __nv_bfloat16  g_wq[(size_t)QD  * Hh];
__device__ __nv_bfloat16  g_wk[(size_t)KVD * Hh];
__device__ __nv_bfloat16  g_wv[(size_t)KVD * Hh];
__device__ __nv_bfloat16  g_wo[(size_t)Hh  * QD];
__device__ __nv_bfloat16  g_vhi[(size_t)Bb * NKVh * HDd * Ss];
__device__ __nv_bfloat16  g_vlo[(size_t)Bb * NKVh * HDd * Ss];
__device__ double         g_absum[4];
__device__ float          g_gamma[4];

// ---------------- helpers ----------------
__device__ __forceinline__ uint32_t smem_u32(const void* p) {
    uint32_t a;
    asm("{ .reg .u64 t; cvta.to.shared.u64 t, %1; cvt.u32.u64 %0, t; }" : "=r"(a) : "l"(p));
    return a;
}
__device__ __forceinline__ uint32_t packbf(float a, float b) {
    __nv_bfloat162 t = __floats2bfloat162_rn(a, b);
    return *(uint32_t*)&t;
}
__device__ __forceinline__ void mma16816(float* c, const uint32_t* a, const uint32_t* b) {
    asm volatile(
        "mma.sync.aligned.m16n8k16.row.col.f32.bf16.bf16.f32 "
        "{%0,%1,%2,%3}, {%4,%5,%6,%7}, {%8,%9}, {%0,%1,%2,%3};"
        : "+f"(c[0]), "+f"(c[1]), "+f"(c[2]), "+f"(c[3])
        : "r"(a[0]), "r"(a[1]), "r"(a[2]), "r"(a[3]), "r"(b[0]), "r"(b[1]));
}
#define CP_ASYNC16(dst, src) \
    asm volatile("cp.async.cg.shared.global [%0], [%1], 16;" :: "r"(dst), "l"(src))
#define CP_COMMIT() asm volatile("cp.async.commit_group;" ::: "memory")
#define CP_WAIT1()  asm volatile("cp.async.wait_group 1;" ::: "memory")
#define CP_WAIT0()  asm volatile("cp.async.wait_group 0;" ::: "memory")

constexpr int ST = 40;   // bf16 smem row stride for 32-wide k-chunks

// ---------------- gamma: abs-sum reduction (float4) ----------------
__global__ void init_kernel() {
    if (threadIdx.x < 4) g_absum[threadIdx.x] = 0.0;
}

__global__ void abssum_kernel(const float4* __restrict__ w, size_t n4, int idx) {
    float s = 0.f;
    for (size_t i = (size_t)blockIdx.x * blockDim.x + threadIdx.x; i < n4;
         i += (size_t)gridDim.x * blockDim.x) {
        float4 v = w[i];
        s += fabsf(v.x) + fabsf(v.y) + fabsf(v.z) + fabsf(v.w);
    }
    __shared__ double sh[256];
    sh[threadIdx.x] = (double)s;
    __syncthreads();
    for (int o = 128; o > 0; o >>= 1) {
        if ((int)threadIdx.x < o) sh[threadIdx.x] += sh[threadIdx.x + o];
        __syncthreads();
    }
    if (threadIdx.x == 0) atomicAdd(&g_absum[idx], sh[0]);
}

// ---------------- ternary quantization -> bf16 plane ----------------
__global__ void quantize_kernel(const float4* __restrict__ w,
                                __nv_bfloat162* __restrict__ t, size_t n4, int idx) {
    float gamma = (float)(g_absum[idx] / (double)(n4 * 4)) + 1e-5f;
    if (blockIdx.x == 0 && threadIdx.x == 0) g_gamma[idx] = gamma;
    for (size_t i = (size_t)blockIdx.x * blockDim.x + threadIdx.x; i < n4;
         i += (size_t)gridDim.x * blockDim.x) {
        float4 v = w[i];
        float rx = fminf(1.f, fmaxf(-1.f, rintf(v.x / gamma)));
        float ry = fminf(1.f, fmaxf(-1.f, rintf(v.y / gamma)));
        float rz = fminf(1.f, fmaxf(-1.f, rintf(v.z / gamma)));
        float rw = fminf(1.f, fmaxf(-1.f, rintf(v.w / gamma)));
        t[2 * i]     = __floats2bfloat162_rn(rx, ry);
        t[2 * i + 1] = __floats2bfloat162_rn(rz, rw);
    }
}

// ---------------- fp32 -> (hi,lo) bf16 planes ----------------
__global__ void split2_kernel(const float4* __restrict__ x,
                              __nv_bfloat162* __restrict__ hi,
                              __nv_bfloat162* __restrict__ lo, size_t n4) {
    for (size_t i = (size_t)blockIdx.x * blockDim.x + threadIdx.x; i < n4;
         i += (size_t)gridDim.x * blockDim.x) {
        float4 f = x[i];
        __nv_bfloat162 hxy = __floats2bfloat162_rn(f.x, f.y);
        __nv_bfloat162 hzw = __floats2bfloat162_rn(f.z, f.w);
        hi[2 * i]     = hxy;
        hi[2 * i + 1] = hzw;
        lo[2 * i]     = __floats2bfloat162_rn(f.x - __bfloat162float(hxy.x),
                                              f.y - __bfloat162float(hxy.y));
        lo[2 * i + 1] = __floats2bfloat162_rn(f.z - __bfloat162float(hzw.x),
                                              f.w - __bfloat162float(hzw.y));
    }
}

// ---------------- V -> transposed hi/lo planes: vt[bk][d][s] ----------------
__global__ void vsplit_kernel() {
    size_t idx = (size_t)blockIdx.x * blockDim.x + threadIdx.x;
    if (idx >= (size_t)Bb * NKVh * HDd * Ss) return;
    int s  = (int)(idx & (Ss - 1));
    int d  = (int)((idx >> 10) & 127);
    int bk = (int)(idx >> 17);
    int b  = bk >> 3, kv = bk & 7;
    float v = g_v[((size_t)(b * Ss + s)) * KVD + kv * HDd + d];
    __nv_bfloat16 h = __float2bfloat16_rn(v);
    g_vhi[idx] = h;
    g_vlo[idx] = __float2bfloat16_rn(v - __bfloat162float(h));
}

// ================= cp.async-pipelined projection GEMM (128x128 tile, 2-stage) =================
constexpr int PLANE   = 128 * ST;
constexpr int GM_SMEM = 2 * 3 * PLANE * 2;        // 61440 B

__global__ __launch_bounds__(256) void gemm_mma2(
    const __nv_bfloat16* __restrict__ Ahi, const __nv_bfloat16* __restrict__ Alo,
    const __nv_bfloat16* __restrict__ W, float* __restrict__ C,
    int N, int K, int gidx)
{
    extern __shared__ __align__(16) __nv_bfloat16 sb[];
    const uint32_t ubase = smem_u32(sb);

    const int tid  = threadIdx.x;
    const int wid  = tid >> 5;
    const int lane = tid & 31;
    const int g    = lane >> 2;
    const int t    = lane & 3;
    const int m0   = blockIdx.y * 128;
    const int n0   = blockIdx.x * 128;
    const int wrow = (wid >> 2) * 64;
    const int wcol = (wid & 3) * 32;

    const int r0 = (tid * 2)     >> 2, c0 = ((tid * 2)     & 3) * 8;
    const int r1 = (tid * 2 + 1) >> 2, c1 = ((tid * 2 + 1) & 3) * 8;

    float acc[4][4][4];
#pragma unroll
    for (int i = 0; i < 4; i++)
#pragma unroll
        for (int j = 0; j < 4; j++)
#pragma unroll
            for (int r = 0; r < 4; r++) acc[i][j][r] = 0.f;

    const int iters = K >> 5;

    auto issue = [&](int it, int stg) {
        const int kc = it << 5;
        uint32_t s0 = ubase + (uint32_t)(stg * 3 * PLANE) * 2;
        CP_ASYNC16(s0 + (r0 * ST + c0) * 2,               &Ahi[(size_t)(m0 + r0) * K + kc + c0]);
        CP_ASYNC16(s0 + (r1 * ST + c1) * 2,               &Ahi[(size_t)(m0 + r1) * K + kc + c1]);
        CP_ASYNC16(s0 + (PLANE + r0 * ST + c0) * 2,       &Alo[(size_t)(m0 + r0) * K + kc + c0]);
        CP_ASYNC16(s0 + (PLANE + r1 * ST + c1) * 2,       &Alo[(size_t)(m0 + r1) * K + kc + c1]);
        CP_ASYNC16(s0 + (2 * PLANE + r0 * ST + c0) * 2,   &W[(size_t)(n0 + r0) * K + kc + c0]);
        CP_ASYNC16(s0 + (2 * PLANE + r1 * ST + c1) * 2,   &W[(size_t)(n0 + r1) * K + kc + c1]);
        CP_COMMIT();
    };

    issue(0, 0);
    for (int it = 0; it < iters; ++it) {
        const int stg = it & 1;
        if (it + 1 < iters) { issue(it + 1, stg ^ 1); CP_WAIT1(); }
        else                { CP_WAIT0(); }
        __syncthreads();

        const __nv_bfloat16* sah = sb + stg * 3 * PLANE;
        const __nv_bfloat16* sal = sah + PLANE;
        const __nv_bfloat16* sbw = sah + 2 * PLANE;

#pragma unroll
        for (int kk = 0; kk < 32; kk += 16) {
            uint32_t ah[4][4], al[4][4], bf[4][2];
#pragma unroll
            for (int mt = 0; mt < 4; mt++) {
                int m = wrow + mt * 16 + g;
                ah[mt][0] = *(const uint32_t*)&sah[(m    ) * ST + kk + 2 * t    ];
                ah[mt][1] = *(const uint32_t*)&sah[(m + 8) * ST + kk + 2 * t    ];
                ah[mt][2] = *(const uint32_t*)&sah[(m    ) * ST + kk + 2 * t + 8];
                ah[mt][3] = *(const uint32_t*)&sah[(m + 8) * ST + kk + 2 * t + 8];
                al[mt][0] = *(const uint32_t*)&sal[(m    ) * ST + kk + 2 * t    ];
                al[mt][1] = *(const uint32_t*)&sal[(m + 8) * ST + kk + 2 * t    ];
                al[mt][2] = *(const uint32_t*)&sal[(m    ) * ST + kk + 2 * t + 8];
                al[mt][3] = *(const uint32_t*)&sal[(m + 8) * ST + kk + 2 * t + 8];
            }
#pragma unroll
            for (int nt = 0; nt < 4; nt++) {
                int n = wcol + nt * 8 + g;
                bf[nt][0] = *(const uint32_t*)&sbw[n * ST + kk + 2 * t    ];
                bf[nt][1] = *(const uint32_t*)&sbw[n * ST + kk + 2 * t + 8];
            }
#pragma unroll
            for (int mt = 0; mt < 4; mt++)
#pragma unroll
                for (int nt = 0; nt < 4; nt++) {
                    mma16816(acc[mt][nt], ah[mt], bf[nt]);
                    mma16816(acc[mt][nt], al[mt], bf[nt]);
                }
        }
        __syncthreads();
    }

    const float gamma = g_gamma[gidx];
#pragma unroll
    for (int mt = 0; mt < 4; mt++) {
#pragma unroll
        for (int nt = 0; nt < 4; nt++) {
            int m = m0 + wrow + mt * 16 + g;
            int n = n0 + wcol + nt * 8 + 2 * t;
            float2 lo = make_float2(acc[mt][nt][0] * gamma, acc[mt][nt][1] * gamma);
            float2 hi = make_float2(acc[mt][nt][2] * gamma, acc[mt][nt][3] * gamma);
            *(float2*)&C[(size_t)m * N + n]       = lo;
            *(float2*)&C[(size_t)(m + 8) * N + n] = hi;
        }
    }
}

// ---------------- RoPE (in place), uses position_ids ----------------
__global__ void rope_kernel(float* __restrict__ x, int nheads,
                            const int* __restrict__ pos_ids) {
    size_t idx = (size_t)blockIdx.x * blockDim.x + threadIdx.x;
    size_t total = (size_t)MTOK * nheads * 64;
    if (idx >= total) return;
    int d = (int)(idx & 63);
    size_t th = idx >> 6;
    int head = (int)(th % nheads);
    size_t tok = th / nheads;
    int pos = pos_ids[tok];
    float inv_freq = 1.0f / powf(10000.0f, (float)d * (1.0f / 64.0f));
    float fr = (float)pos * inv_freq;
    float s, c;
    sincosf(fr, &s, &c);
    float* base = x + tok * ((size_t)nheads * HDd) + (size_t)head * HDd;
    float x1 = base[d], x2 = base[d + 64];
    base[d]      = x1 * c - x2 * s;
    base[d + 64] = x2 * c + x1 * s;
}

// ================= fused flash attention (R13 champion version) =================
// smem layout (bytes):
//   [0      : 10240)  sqh   (128 x ST bf16)
//   [10240  : 20480)  sql
//   [20480  : 30720)  skh
//   [30720  : 40960)  skl
//   [40960  : 43008)  red   (128 x 4 float)
//   [43008  : 77824)  Ph    (128 x 136 bf16)
//   [77824  : 112640) Pl
//   [112640 : 147456) Svh   (V^T hi, 128 x 136 bf16)
//   [147456 : 182272) Svl
constexpr int PST = 136;
constexpr int FL_SMEM = 182272;

__global__ __launch_bounds__(256) void flash_mma() {
    extern __shared__ char ds[];
    __nv_bfloat16* sqh = (__nv_bfloat16*)(ds);
    __nv_bfloat16* sql = (__nv_bfloat16*)(ds + 10240);
    __nv_bfloat16* skh = (__nv_bfloat16*)(ds + 20480);
    __nv_bfloat16* skl = (__nv_bfloat16*)(ds + 30720);
    float*         red = (float*)        (ds + 40960);
    __nv_bfloat16* Ph  = (__nv_bfloat16*)(ds + 43008);
    __nv_bfloat16* Pl  = (__nv_bfloat16*)(ds + 77824);
    __nv_bfloat16* Svh = (__nv_bfloat16*)(ds + 112640);
    __nv_bfloat16* Svl = (__nv_bfloat16*)(ds + 147456);

    const int bh = blockIdx.y;
    const int b = bh >> 5, h = bh & 31;
    const int kvh = h >> 2;
    const int bk = b * NKVh + kvh;
    const int m0 = blockIdx.x * 128;

    const float* __restrict__ Q  = g_q + (size_t)b * Ss * QD  + (size_t)h * HDd;
    const float* __restrict__ Kp = g_k + (size_t)b * Ss * KVD + (size_t)kvh * HDd;
    const __nv_bfloat16* __restrict__ Vh = g_vhi + (size_t)bk * HDd * Ss;
    const __nv_bfloat16* __restrict__ Vl = g_vlo + (size_t)bk * HDd * Ss;
    __nv_bfloat16* __restrict__ Ohi = g_ahi + (size_t)b * Ss * QD + (size_t)h * HDd;
    __nv_bfloat16* __restrict__ Olo = g_alo + (size_t)b * Ss * QD + (size_t)h * HDd;

    const int tid  = threadIdx.x;
    const int wid  = tid >> 5;
    const int lane = tid & 31;
    const int g    = lane >> 2;
    const int t    = lane & 3;
    const int wrow = (wid >> 2) * 64;
    const int wcol = (wid & 3) * 32;
    const int wc   = wid & 3;
    const float scale = 0.08838834764831845f;  // 1/sqrt(128)

    float oacc[4][4][4];
    float M[8], L[8];
#pragma unroll
    for (int i = 0; i < 4; i++)
#pragma unroll
        for (int j = 0; j < 4; j++)
#pragma unroll
            for (int r = 0; r < 4; r++) oacc[i][j][r] = 0.f;
#pragma unroll
    for (int i = 0; i < 8; i++) { M[i] = -INFINITY; L[i] = 0.f; }

    for (int n0 = 0; n0 <= m0; n0 += 128) {
        // ---------- QK: s = Q . K^T ----------
        float s[4][4][4];
#pragma unroll
        for (int i = 0; i < 4; i++)
#pragma unroll
            for (int j = 0; j < 4; j++)
#pragma unroll
                for (int r = 0; r < 4; r++) s[i][j][r] = 0.f;

        for (int kc = 0; kc < HDd; kc += 32) {
#pragma unroll
            for (int l = 0; l < 4; l++) {
                int seg = tid + l * 256;
                int row = seg >> 3;
                int c4  = (seg & 7) * 4;
                float4 va = *(const float4*)&Q[(size_t)(m0 + row) * QD + kc + c4];
                float hx = __bfloat162float(__float2bfloat16_rn(va.x));
                float hy = __bfloat162float(__float2bfloat16_rn(va.y));
                float hz = __bfloat162float(__float2bfloat16_rn(va.z));
                float hw = __bfloat162float(__float2bfloat16_rn(va.w));
                *(uint32_t*)&sqh[row * ST + c4]     = packbf(hx, hy);
                *(uint32_t*)&sqh[row * ST + c4 + 2] = packbf(hz, hw);
                *(uint32_t*)&sql[row * ST + c4]     = packbf(va.x - hx, va.y - hy);
                *(uint32_t*)&sql[row * ST + c4 + 2] = packbf(va.z - hz, va.w - hw);

                float4 vb = *(const float4*)&Kp[(size_t)(n0 + row) * KVD + kc + c4];
                float gx = __bfloat162float(__float2bfloat16_rn(vb.x));
                float gy = __bfloat162float(__float2bfloat16_rn(vb.y));
                float gz = __bfloat162float(__float2bfloat16_rn(vb.z));
                float gw = __bfloat162float(__float2bfloat16_rn(vb.w));
                *(uint32_t*)&skh[row * ST + c4]     = packbf(gx, gy);
                *(uint32_t*)&skh[row * ST + c4 + 2] = packbf(gz, gw);
                *(uint32_t*)&skl[row * ST + c4]     = packbf(vb.x - gx, vb.y - gy);
                *(uint32_t*)&skl[row * ST + c4 + 2] = packbf(vb.z - gz, vb.w - gw);
            }
            __syncthreads();
#pragma unroll
            for (int kk = 0; kk < 32; kk += 16) {
                uint32_t ah[4][4], al[4][4], bh2[4][2], bl2[4][2];
#pragma unroll
                for (int mt = 0; mt < 4; mt++) {
                    int m = wrow + mt * 16 + g;
                    ah[mt][0] = *(const uint32_t*)&sqh[(m    ) * ST + kk + 2 * t    ];
                    ah[mt][1] = *(const uint32_t*)&sqh[(m + 8) * ST + kk + 2 * t    ];
                    ah[mt][2] = *(const uint32_t*)&sqh[(m    ) * ST + kk + 2 * t + 8];
                    ah[mt][3] = *(const uint32_t*)&sqh[(m + 8) * ST + kk + 2 * t + 8];
                    al[mt][0] = *(const uint32_t*)&sql[(m    ) * ST + kk + 2 * t    ];
                    al[mt][1] = *(const uint32_t*)&sql[(m + 8) * ST + kk + 2 * t    ];
                    al[mt][2] = *(const uint32_t*)&sql[(m    ) * ST + kk + 2 * t + 8];
                    al[mt][3] = *(const uint32_t*)&sql[(m + 8) * ST + kk + 2 * t + 8];
                }
#pragma unroll
                for (int nt = 0; nt < 4; nt++) {
                    int n = wcol + nt * 8 + g;
                    bh2[nt][0] = *(const uint32_t*)&skh[n * ST + kk + 2 * t    ];
                    bh2[nt][1] = *(const uint32_t*)&skh[n * ST + kk + 2 * t + 8];
                    bl2[nt][0] = *(const uint32_t*)&skl[n * ST + kk + 2 * t    ];
                    bl2[nt][1] = *(const uint32_t*)&skl[n * ST + kk + 2 * t + 8];
                }
#pragma unroll
                for (int mt = 0; mt < 4; mt++)
#pragma unroll
                    for (int nt = 0; nt < 4; nt++) {
                        mma16816(s[mt][nt], ah[mt], bh2[nt]);
                        mma16816(s[mt][nt], al[mt], bh2[nt]);
                        mma16816(s[mt][nt], ah[mt], bl2[nt]);
                    }
            }
            __syncthreads();
        }

        // ---------- load V^T tile (hi/lo), 128 x 128, stride PST ----------
#pragma unroll
        for (int l = 0; l < 8; l++) {
            int seg = tid + l * 256;
            int row = seg >> 4;
            int cs  = (seg & 15) * 8;
            *(uint4*)&Svh[row * PST + cs] = *(const uint4*)&Vh[(size_t)row * Ss + n0 + cs];
            *(uint4*)&Svl[row * PST + cs] = *(const uint4*)&Vl[(size_t)row * Ss + n0 + cs];
        }

        // ---------- scale + causal mask + tile row-max ----------
        float tstat[8];
#pragma unroll
        for (int mt = 0; mt < 4; mt++) {
#pragma unroll
            for (int half = 0; half < 2; half++) {
                int rl = wrow + mt * 16 + g + half * 8;
                float mx = -INFINITY;
#pragma unroll
                for (int nt = 0; nt < 4; nt++) {
#pragma unroll
                    for (int j = 0; j < 2; j++) {
                        int cl = wcol + nt * 8 + 2 * t + j;
                        float sv = s[mt][nt][half * 2 + j] * scale;
                        bool ok = (n0 + cl) <= (m0 + rl);
                        sv = ok ? sv : -INFINITY;
                        s[mt][nt][half * 2 + j] = sv;
                        mx = fmaxf(mx, sv);
                    }
                }
                mx = fmaxf(mx, __shfl_xor_sync(0xffffffffu, mx, 1));
                mx = fmaxf(mx, __shfl_xor_sync(0xffffffffu, mx, 2));
                tstat[mt * 2 + half] = mx;
            }
        }
        if (t == 0) {
#pragma unroll
            for (int mt = 0; mt < 4; mt++)
#pragma unroll
                for (int half = 0; half < 2; half++) {
                    int rl = wrow + mt * 16 + g + half * 8;
                    red[rl * 4 + wc] = tstat[mt * 2 + half];
                }
        }
        __syncthreads();

        float Mn[8], alpha[8];
#pragma unroll
        for (int mt = 0; mt < 4; mt++) {
#pragma unroll
            for (int half = 0; half < 2; half++) {
                int i = mt * 2 + half;
                int rl = wrow + mt * 16 + g + half * 8;
                float tm = fmaxf(fmaxf(red[rl * 4 + 0], red[rl * 4 + 1]),
                                 fmaxf(red[rl * 4 + 2], red[rl * 4 + 3]));
                Mn[i] = fmaxf(M[i], tm);
                alpha[i] = expf(M[i] - Mn[i]);
                M[i] = Mn[i];
            }
        }
        __syncthreads();   // red reused for sums

        // ---------- p = exp(s - M), write P hi/lo to smem, row sums ----------
#pragma unroll
        for (int mt = 0; mt < 4; mt++) {
#pragma unroll
            for (int half = 0; half < 2; half++) {
                int i = mt * 2 + half;
                int rl = wrow + mt * 16 + g + half * 8;
                float sm = 0.f;
#pragma unroll
                for (int nt = 0; nt < 4; nt++) {
                    float pa = expf(s[mt][nt][half * 2 + 0] - M[i]);
                    float pb = expf(s[mt][nt][half * 2 + 1] - M[i]);
                    sm += pa + pb;
                    float ha = __bfloat162float(__float2bfloat16_rn(pa));
                    float hb = __bfloat162float(__float2bfloat16_rn(pb));
                    int cl = wcol + nt * 8 + 2 * t;
                    *(uint32_t*)&Ph[rl * PST + cl] = packbf(ha, hb);
                    *(uint32_t*)&Pl[rl * PST + cl] = packbf(pa - ha, pb - hb);
                }
                sm += __shfl_xor_sync(0xffffffffu, sm, 1);
                sm += __shfl_xor_sync(0xffffffffu, sm, 2);
                tstat[i] = sm;
            }
        }
        if (t == 0) {
#pragma unroll
            for (int mt = 0; mt < 4; mt++)
#pragma unroll
                for (int half = 0; half < 2; half++) {
                    int rl = wrow + mt * 16 + g + half * 8;
                    red[rl * 4 + wc] = tstat[mt * 2 + half];
                }
        }
        __syncthreads();

#pragma unroll
        for (int mt = 0; mt < 4; mt++) {
#pragma unroll
            for (int half = 0; half < 2; half++) {
                int i = mt * 2 + half;
                int rl = wrow + mt * 16 + g + half * 8;
                float rs = red[rl * 4 + 0] + red[rl * 4 + 1] +
                           red[rl * 4 + 2] + red[rl * 4 + 3];
                L[i] = L[i] * alpha[i] + rs;
            }
        }
#pragma unroll
        for (int mt = 0; mt < 4; mt++)
#pragma unroll
            for (int nt = 0; nt < 4; nt++) {
                oacc[mt][nt][0] *= alpha[mt * 2 + 0];
                oacc[mt][nt][1] *= alpha[mt * 2 + 0];
                oacc[mt][nt][2] *= alpha[mt * 2 + 1];
                oacc[mt][nt][3] *= alpha[mt * 2 + 1];
            }

        // ---------- PV: O += P . V^T ----------
#pragma unroll
        for (int kk = 0; kk < 128; kk += 16) {
            uint32_t ah[4][4], al[4][4], bh2[4][2], bl2[4][2];
#pragma unroll
            for (int mt = 0; mt < 4; mt++) {
                int m = wrow + mt * 16 + g;
                ah[mt][0] = *(const uint32_t*)&Ph[(m    ) * PST + kk + 2 * t    ];
                ah[mt][1] = *(const uint32_t*)&Ph[(m + 8) * PST + kk + 2 * t    ];
                ah[mt][2] = *(const uint32_t*)&Ph[(m    ) * PST + kk + 2 * t + 8];
                ah[mt][3] = *(const uint32_t*)&Ph[(m + 8) * PST + kk + 2 * t + 8];
                al[mt][0] = *(const uint32_t*)&Pl[(m    ) * PST + kk + 2 * t    ];
                al[mt][1] = *(const uint32_t*)&Pl[(m + 8) * PST + kk + 2 * t    ];
                al[mt][2] = *(const uint32_t*)&Pl[(m    ) * PST + kk + 2 * t + 8];
                al[mt][3] = *(const uint32_t*)&Pl[(m + 8) * PST + kk + 2 * t + 8];
            }
#pragma unroll
            for (int nt = 0; nt < 4; nt++) {
                int n = wcol + nt * 8 + g;
                bh2[nt][0] = *(const uint32_t*)&Svh[n * PST + kk + 2 * t    ];
                bh2[nt][1] = *(const uint32_t*)&Svh[n * PST + kk + 2 * t + 8];
                bl2[nt][0] = *(const uint32_t*)&Svl[n * PST + kk + 2 * t    ];
                bl2[nt][1] = *(const uint32_t*)&Svl[n * PST + kk + 2 * t + 8];
            }
#pragma unroll
            for (int mt = 0; mt < 4; mt++)
#pragma unroll
                for (int nt = 0; nt < 4; nt++) {
                    mma16816(oacc[mt][nt], ah[mt], bh2[nt]);
                    mma16816(oacc[mt][nt], al[mt], bh2[nt]);
                    mma16816(oacc[mt][nt], ah[mt], bl2[nt]);
                }
        }
        __syncthreads();
    }

    // ---------- epilogue: O /= L, write hi/lo bf16 planes ----------
    float inv[8];
#pragma unroll
    for (int i = 0; i < 8; i++) inv[i] = 1.f / L[i];
#pragma unroll
    for (int mt = 0; mt < 4; mt++) {
#pragma unroll
        for (int nt = 0; nt < 4; nt++) {
            int m = m0 + wrow + mt * 16 + g;
            int n = wcol + nt * 8 + 2 * t;
            float v0 = oacc[mt][nt][0] * inv[mt * 2 + 0];
            float v1 = oacc[mt][nt][1] * inv[mt * 2 + 0];
            float h0 = __bfloat162float(__float2bfloat16_rn(v0));
            float h1 = __bfloat162float(__float2bfloat16_rn(v1));
            *(uint32_t*)&Ohi[(size_t)m * QD + n] = packbf(h0, h1);
            *(uint32_t*)&Olo[(size_t)m * QD + n] = packbf(v0 - h0, v1 - h1);

            float v2 = oacc[mt][nt][2] * inv[mt * 2 + 1];
            float v3 = oacc[mt][nt][3] * inv[mt * 2 + 1];
            float h2 = __bfloat162float(__float2bfloat16_rn(v2));
            float h3 = __bfloat162float(__float2bfloat16_rn(v3));
            *(uint32_t*)&Ohi[(size_t)(m + 8) * QD + n] = packbf(h2, h3);
            *(uint32_t*)&Olo[(size_t)(m + 8) * QD + n] = packbf(v2 - h2, v3 - h3);
        }
    }
}

// ---------------- launch ----------------
extern "C" void kernel_launch(void* const* d_in, const int* in_sizes, int n_in,
                              void* d_out, int out_size)
{
    const float* hidden = nullptr;
    const float* big16[2] = {nullptr, nullptr};
    const float* sml4[2]  = {nullptr, nullptr};
    const int*   posid = nullptr;
    int hidden_idx = -1, nb = 0, ns = 0;
    for (int i = 0; i < n_in; i++) {
        if (in_sizes[i] == 8388608)               { hidden = (const float*)d_in[i]; hidden_idx = i; }
        else if (in_sizes[i] == 16777216 && nb<2) { big16[nb++] = (const float*)d_in[i]; }
        else if (in_sizes[i] == 4194304  && ns<2) { sml4[ns++]  = (const float*)d_in[i]; }
        else if (in_sizes[i] == 2048)             { posid = (const int*)d_in[i]; }
    }
    const float* Wq = (hidden_idx == 0) ? big16[0] : big16[1];
    const float* Wo = (hidden_idx == 0) ? big16[1] : big16[0];
    const float* Wk = sml4[0];
    const float* Wv = sml4[1];
    float* out = (float*)d_out;

    void *pq, *pk, *pv, *pahi, *palo, *pwq, *pwk, *pwv, *pwo;
    cudaGetSymbolAddress(&pq, g_q);
    cudaGetSymbolAddress(&pk, g_k);
    cudaGetSymbolAddress(&pv, g_v);
    cudaGetSymbolAddress(&pahi, g_ahi);
    cudaGetSymbolAddress(&palo, g_alo);
    cudaGetSymbolAddress(&pwq, g_wq);
    cudaGetSymbolAddress(&pwk, g_wk);
    cudaGetSymbolAddress(&pwv, g_wv);
    cudaGetSymbolAddress(&pwo, g_wo);

    cudaFuncSetAttribute(gemm_mma2, cudaFuncAttributeMaxDynamicSharedMemorySize, GM_SMEM);
    cudaFuncSetAttribute(flash_mma, cudaFuncAttributeMaxDynamicSharedMemorySize, FL_SMEM);

    const size_t nQ4 = (size_t)QD * Hh / 4;
    const size_t nK4 = (size_t)KVD * Hh / 4;
    const size_t nO4 = (size_t)Hh * QD / 4;
    const size_t nH4 = (size_t)MTOK * Hh / 4;

    // Streams/events created once (during the pre-capture correctness call) so
    // graph capture performs no driver allocations.
    static cudaStream_t s2 = nullptr;
    static cudaEvent_t ev0, evQw, evK, evV, evO, evVg, evVS;
    if (s2 == nullptr) {
        cudaStreamCreateWithFlags(&s2, cudaStreamNonBlocking);
        cudaEventCreateWithFlags(&ev0, cudaEventDisableTiming);
        cudaEventCreateWithFlags(&evQw, cudaEventDisableTiming);
        cudaEventCreateWithFlags(&evK, cudaEventDisableTiming);
        cudaEventCreateWithFlags(&evV, cudaEventDisableTiming);
        cudaEventCreateWithFlags(&evO, cudaEventDisableTiming);
        cudaEventCreateWithFlags(&evVg, cudaEventDisableTiming);
        cudaEventCreateWithFlags(&evVS, cudaEventDisableTiming);
    }

    init_kernel<<<1, 32>>>();
    cudaEventRecord(ev0, 0);
    cudaStreamWaitEvent(s2, ev0, 0);

    // side stream: ALL weight preprocessing (Wq first so gemmQ can start ASAP)
    abssum_kernel<<<2048, 256, 0, s2>>>((const float4*)Wq, nQ4, 0);
    quantize_kernel<<<4096, 256, 0, s2>>>((const float4*)Wq, (__nv_bfloat162*)pwq, nQ4, 0);
    cudaEventRecord(evQw, s2);
    abssum_kernel<<<2048, 256, 0, s2>>>((const float4*)Wk, nK4, 1);
    quantize_kernel<<<4096, 256, 0, s2>>>((const float4*)Wk, (__nv_bfloat162*)pwk, nK4, 1);
    cudaEventRecord(evK, s2);
    abssum_kernel<<<2048, 256, 0, s2>>>((const float4*)Wv, nK4, 2);
    quantize_kernel<<<4096, 256, 0, s2>>>((const float4*)Wv, (__nv_bfloat162*)pwv, nK4, 2);
    cudaEventRecord(evV, s2);
    abssum_kernel<<<2048, 256, 0, s2>>>((const float4*)Wo, nO4, 3);
    quantize_kernel<<<4096, 256, 0, s2>>>((const float4*)Wo, (__nv_bfloat162*)pwo, nO4, 3);
    cudaEventRecord(evO, s2);

    // main stream: activation split runs concurrently with Wq preprocessing
    split2_kernel<<<4096, 256>>>((const float4*)hidden, (__nv_bfloat162*)pahi,
                                 (__nv_bfloat162*)palo, nH4);
    cudaStreamWaitEvent(0, evQw, 0);
    gemm_mma2<<<dim3(QD / 128, MTOK / 128), 256, GM_SMEM>>>(
        (const __nv_bfloat16*)pahi, (const __nv_bfloat16*)palo,
        (const __nv_bfloat16*)pwq, (float*)pq, QD, Hh, 0);

    cudaStreamWaitEvent(0, evK, 0);
    gemm_mma2<<<dim3(KVD / 128, MTOK / 128), 256, GM_SMEM>>>(
        (const __nv_bfloat16*)pahi, (const __nv_bfloat16*)palo,
        (const __nv_bfloat16*)pwk, (float*)pk, KVD, Hh, 1);
    cudaStreamWaitEvent(0, evV, 0);
    gemm_mma2<<<dim3(KVD / 128, MTOK / 128), 256, GM_SMEM>>>(
        (const __nv_bfloat16*)pahi, (const __nv_bfloat16*)palo,
        (const __nv_bfloat16*)pwv, (float*)pv, KVD, Hh, 2);
    cudaEventRecord(evVg, 0);

    // side stream: V transpose/split overlaps rope
    cudaStreamWaitEvent(s2, evVg, 0);
    vsplit_kernel<<<(int)(((size_t)Bb * NKVh * HDd * Ss + 255) / 256), 256, 0, s2>>>();
    cudaEventRecord(evVS, s2);

    rope_kernel<<<(int)(((size_t)MTOK * NHq * 64 + 255) / 256), 256>>>((float*)pq, NHq, posid);
    rope_kernel<<<(int)(((size_t)MTOK * NKVh * 64 + 255) / 256), 256>>>((float*)pk, NKVh, posid);

    cudaStreamWaitEvent(0, evVS, 0);
    flash_mma<<<dim3(Ss / 128, Bb * NHq), 256, FL_SMEM>>>();

    cudaStreamWaitEvent(0, evO, 0);
    gemm_mma2<<<dim3(Hh / 128, MTOK / 128), 256, GM_SMEM>>>(
        (const __nv_bfloat16*)pahi, (const __nv_bfloat16*)palo,
        (const __nv_bfloat16*)pwo, out, Hh, QD, 3);
}

// round 17
// speedup vs baseline: 1.1563x; 1.0098x over previous
#include <cuda_runtime.h>
#include <cuda_bf16.h>
#include <math.h>
#include <stdint.h>

// Problem constants
constexpr int Bb   = 2;
constexpr int Ss   = 1024;
constexpr int Hh   = 4096;
constexpr int NHq  = 32;
constexpr int NKVh = 8;
constexpr int HDd  = 128;
constexpr int MTOK = Bb * Ss;             // 2048
constexpr int QD   = NHq * HDd;           // 4096
constexpr int KVD  = NKVh * HDd;          // 1024

// ---------------- device scratch (static; allocation-free) ----------------
__device__ float          g_q[(size_t)MTOK * QD];
__device__ float          g_k[(size_t)MTOK * KVD];
__device__ float          g_v[(size_t)MTOK * KVD];
__device__ __nv_bfloat16  g_ahi[(size_t)MTOK * Hh];
__device__ __nv_bfloat16  g_alo[(size_t)MTOK * Hh];
__device__ __nv_bfloat16  g_wq[(size_t)QD  * Hh];
__device__ __nv_bfloat16  g_wk[(size_t)KVD * Hh];
__device__ __nv_bfloat16  g_wv[(size_t)KVD * Hh];
__device__ __nv_bfloat16  g_wo[(size_t)Hh  * QD];
__device__ __nv_bfloat16  g_vhi[(size_t)Bb * NKVh * HDd * Ss];
__device__ __nv_bfloat16  g_vlo[(size_t)Bb * NKVh * HDd * Ss];
__device__ double         g_absum[4];
__device__ float          g_gamma[4];

// ---------------- helpers ----------------
__device__ __forceinline__ uint32_t smem_u32(const void* p) {
    uint32_t a;
    asm("{ .reg .u64 t; cvta.to.shared.u64 t, %1; cvt.u32.u64 %0, t; }" : "=r"(a) : "l"(p));
    return a;
}
__device__ __forceinline__ uint32_t packbf(float a, float b) {
    __nv_bfloat162 t = __floats2bfloat162_rn(a, b);
    return *(uint32_t*)&t;
}
__device__ __forceinline__ void mma16816(float* c, const uint32_t* a, const uint32_t* b) {
    asm volatile(
        "mma.sync.aligned.m16n8k16.row.col.f32.bf16.bf16.f32 "
        "{%0,%1,%2,%3}, {%4,%5,%6,%7}, {%8,%9}, {%0,%1,%2,%3};"
        : "+f"(c[0]), "+f"(c[1]), "+f"(c[2]), "+f"(c[3])
        : "r"(a[0]), "r"(a[1]), "r"(a[2]), "r"(a[3]), "r"(b[0]), "r"(b[1]));
}
#define CP_ASYNC16(dst, src) \
    asm volatile("cp.async.cg.shared.global [%0], [%1], 16;" :: "r"(dst), "l"(src))
#define CP_COMMIT() asm volatile("cp.async.commit_group;" ::: "memory")
#define CP_WAIT1()  asm volatile("cp.async.wait_group 1;" ::: "memory")
#define CP_WAIT0()  asm volatile("cp.async.wait_group 0;" ::: "memory")

constexpr int ST = 40;   // bf16 smem row stride for 32-wide k-chunks

// ---------------- gamma: abs-sum reduction (float4) ----------------
__global__ void init_kernel() {
    if (threadIdx.x < 4) g_absum[threadIdx.x] = 0.0;
}

__global__ void abssum_kernel(const float4* __restrict__ w, size_t n4, int idx) {
    float s = 0.f;
    for (size_t i = (size_t)blockIdx.x * blockDim.x + threadIdx.x; i < n4;
         i += (size_t)gridDim.x * blockDim.x) {
        float4 v = w[i];
        s += fabsf(v.x) + fabsf(v.y) + fabsf(v.z) + fabsf(v.w);
    }
    __shared__ double sh[256];
    sh[threadIdx.x] = (double)s;
    __syncthreads();
    for (int o = 128; o > 0; o >>= 1) {
        if ((int)threadIdx.x < o) sh[threadIdx.x] += sh[threadIdx.x + o];
        __syncthreads();
    }
    if (threadIdx.x == 0) atomicAdd(&g_absum[idx], sh[0]);
}

// ---------------- ternary quantization -> bf16 plane ----------------
__global__ void quantize_kernel(const float4* __restrict__ w,
                                __nv_bfloat162* __restrict__ t, size_t n4, int idx) {
    float gamma = (float)(g_absum[idx] / (double)(n4 * 4)) + 1e-5f;
    if (blockIdx.x == 0 && threadIdx.x == 0) g_gamma[idx] = gamma;
    for (size_t i = (size_t)blockIdx.x * blockDim.x + threadIdx.x; i < n4;
         i += (size_t)gridDim.x * blockDim.x) {
        float4 v = w[i];
        float rx = fminf(1.f, fmaxf(-1.f, rintf(v.x / gamma)));
        float ry = fminf(1.f, fmaxf(-1.f, rintf(v.y / gamma)));
        float rz = fminf(1.f, fmaxf(-1.f, rintf(v.z / gamma)));
        float rw = fminf(1.f, fmaxf(-1.f, rintf(v.w / gamma)));
        t[2 * i]     = __floats2bfloat162_rn(rx, ry);
        t[2 * i + 1] = __floats2bfloat162_rn(rz, rw);
    }
}

// ---------------- fp32 -> (hi,lo) bf16 planes ----------------
__global__ void split2_kernel(const float4* __restrict__ x,
                              __nv_bfloat162* __restrict__ hi,
                              __nv_bfloat162* __restrict__ lo, size_t n4) {
    for (size_t i = (size_t)blockIdx.x * blockDim.x + threadIdx.x; i < n4;
         i += (size_t)gridDim.x * blockDim.x) {
        float4 f = x[i];
        __nv_bfloat162 hxy = __floats2bfloat162_rn(f.x, f.y);
        __nv_bfloat162 hzw = __floats2bfloat162_rn(f.z, f.w);
        hi[2 * i]     = hxy;
        hi[2 * i + 1] = hzw;
        lo[2 * i]     = __floats2bfloat162_rn(f.x - __bfloat162float(hxy.x),
                                              f.y - __bfloat162float(hxy.y));
        lo[2 * i + 1] = __floats2bfloat162_rn(f.z - __bfloat162float(hzw.x),
                                              f.w - __bfloat162float(hzw.y));
    }
}

// ---------------- V -> transposed hi/lo planes: vt[bk][d][s] ----------------
__global__ void vsplit_kernel() {
    size_t idx = (size_t)blockIdx.x * blockDim.x + threadIdx.x;
    if (idx >= (size_t)Bb * NKVh * HDd * Ss) return;
    int s  = (int)(idx & (Ss - 1));
    int d  = (int)((idx >> 10) & 127);
    int bk = (int)(idx >> 17);
    int b  = bk >> 3, kv = bk & 7;
    float v = g_v[((size_t)(b * Ss + s)) * KVD + kv * HDd + d];
    __nv_bfloat16 h = __float2bfloat16_rn(v);
    g_vhi[idx] = h;
    g_vlo[idx] = __float2bfloat16_rn(v - __bfloat162float(h));
}

// ================= cp.async-pipelined projection GEMM (128x128 tile, 2-stage) =================
constexpr int PLANE   = 128 * ST;
constexpr int GM_SMEM = 2 * 3 * PLANE * 2;        // 61440 B

__global__ __launch_bounds__(256) void gemm_mma2(
    const __nv_bfloat16* __restrict__ Ahi, const __nv_bfloat16* __restrict__ Alo,
    const __nv_bfloat16* __restrict__ W, float* __restrict__ C,
    int N, int K, int gidx)
{
    extern __shared__ __align__(16) __nv_bfloat16 sb[];
    const uint32_t ubase = smem_u32(sb);

    const int tid  = threadIdx.x;
    const int wid  = tid >> 5;
    const int lane = tid & 31;
    const int g    = lane >> 2;
    const int t    = lane & 3;
    const int m0   = blockIdx.y * 128;
    const int n0   = blockIdx.x * 128;
    const int wrow = (wid >> 2) * 64;
    const int wcol = (wid & 3) * 32;

    const int r0 = (tid * 2)     >> 2, c0 = ((tid * 2)     & 3) * 8;
    const int r1 = (tid * 2 + 1) >> 2, c1 = ((tid * 2 + 1) & 3) * 8;

    float acc[4][4][4];
#pragma unroll
    for (int i = 0; i < 4; i++)
#pragma unroll
        for (int j = 0; j < 4; j++)
#pragma unroll
            for (int r = 0; r < 4; r++) acc[i][j][r] = 0.f;

    const int iters = K >> 5;

    auto issue = [&](int it, int stg) {
        const int kc = it << 5;
        uint32_t s0 = ubase + (uint32_t)(stg * 3 * PLANE) * 2;
        CP_ASYNC16(s0 + (r0 * ST + c0) * 2,               &Ahi[(size_t)(m0 + r0) * K + kc + c0]);
        CP_ASYNC16(s0 + (r1 * ST + c1) * 2,               &Ahi[(size_t)(m0 + r1) * K + kc + c1]);
        CP_ASYNC16(s0 + (PLANE + r0 * ST + c0) * 2,       &Alo[(size_t)(m0 + r0) * K + kc + c0]);
        CP_ASYNC16(s0 + (PLANE + r1 * ST + c1) * 2,       &Alo[(size_t)(m0 + r1) * K + kc + c1]);
        CP_ASYNC16(s0 + (2 * PLANE + r0 * ST + c0) * 2,   &W[(size_t)(n0 + r0) * K + kc + c0]);
        CP_ASYNC16(s0 + (2 * PLANE + r1 * ST + c1) * 2,   &W[(size_t)(n0 + r1) * K + kc + c1]);
        CP_COMMIT();
    };

    issue(0, 0);
    for (int it = 0; it < iters; ++it) {
        const int stg = it & 1;
        if (it + 1 < iters) { issue(it + 1, stg ^ 1); CP_WAIT1(); }
        else                { CP_WAIT0(); }
        __syncthreads();

        const __nv_bfloat16* sah = sb + stg * 3 * PLANE;
        const __nv_bfloat16* sal = sah + PLANE;
        const __nv_bfloat16* sbw = sah + 2 * PLANE;

#pragma unroll
        for (int kk = 0; kk < 32; kk += 16) {
            uint32_t ah[4][4], al[4][4], bf[4][2];
#pragma unroll
            for (int mt = 0; mt < 4; mt++) {
                int m = wrow + mt * 16 + g;
                ah[mt][0] = *(const uint32_t*)&sah[(m    ) * ST + kk + 2 * t    ];
                ah[mt][1] = *(const uint32_t*)&sah[(m + 8) * ST + kk + 2 * t    ];
                ah[mt][2] = *(const uint32_t*)&sah[(m    ) * ST + kk + 2 * t + 8];
                ah[mt][3] = *(const uint32_t*)&sah[(m + 8) * ST + kk + 2 * t + 8];
                al[mt][0] = *(const uint32_t*)&sal[(m    ) * ST + kk + 2 * t    ];
                al[mt][1] = *(const uint32_t*)&sal[(m + 8) * ST + kk + 2 * t    ];
                al[mt][2] = *(const uint32_t*)&sal[(m    ) * ST + kk + 2 * t + 8];
                al[mt][3] = *(const uint32_t*)&sal[(m + 8) * ST + kk + 2 * t + 8];
            }
#pragma unroll
            for (int nt = 0; nt < 4; nt++) {
                int n = wcol + nt * 8 + g;
                bf[nt][0] = *(const uint32_t*)&sbw[n * ST + kk + 2 * t    ];
                bf[nt][1] = *(const uint32_t*)&sbw[n * ST + kk + 2 * t + 8];
            }
#pragma unroll
            for (int mt = 0; mt < 4; mt++)
#pragma unroll
                for (int nt = 0; nt < 4; nt++) {
                    mma16816(acc[mt][nt], ah[mt], bf[nt]);
                    mma16816(acc[mt][nt], al[mt], bf[nt]);
                }
        }
        __syncthreads();
    }

    const float gamma = g_gamma[gidx];
#pragma unroll
    for (int mt = 0; mt < 4; mt++) {
#pragma unroll
        for (int nt = 0; nt < 4; nt++) {
            int m = m0 + wrow + mt * 16 + g;
            int n = n0 + wcol + nt * 8 + 2 * t;
            float2 lo = make_float2(acc[mt][nt][0] * gamma, acc[mt][nt][1] * gamma);
            float2 hi = make_float2(acc[mt][nt][2] * gamma, acc[mt][nt][3] * gamma);
            *(float2*)&C[(size_t)m * N + n]       = lo;
            *(float2*)&C[(size_t)(m + 8) * N + n] = hi;
        }
    }
}

// ---------------- RoPE (in place), uses position_ids ----------------
__global__ void rope_kernel(float* __restrict__ x, int nheads,
                            const int* __restrict__ pos_ids) {
    size_t idx = (size_t)blockIdx.x * blockDim.x + threadIdx.x;
    size_t total = (size_t)MTOK * nheads * 64;
    if (idx >= total) return;
    int d = (int)(idx & 63);
    size_t th = idx >> 6;
    int head = (int)(th % nheads);
    size_t tok = th / nheads;
    int pos = pos_ids[tok];
    float inv_freq = 1.0f / powf(10000.0f, (float)d * (1.0f / 64.0f));
    float fr = (float)pos * inv_freq;
    float s, c;
    sincosf(fr, &s, &c);
    float* base = x + tok * ((size_t)nheads * HDd) + (size_t)head * HDd;
    float x1 = base[d], x2 = base[d + 64];
    base[d]      = x1 * c - x2 * s;
    base[d + 64] = x2 * c + x1 * s;
}

// ================= fused flash attention (champion version) =================
constexpr int PST = 136;
constexpr int FL_SMEM = 182272;

__global__ __launch_bounds__(256) void flash_mma() {
    extern __shared__ char ds[];
    __nv_bfloat16* sqh = (__nv_bfloat16*)(ds);
    __nv_bfloat16* sql = (__nv_bfloat16*)(ds + 10240);
    __nv_bfloat16* skh = (__nv_bfloat16*)(ds + 20480);
    __nv_bfloat16* skl = (__nv_bfloat16*)(ds + 30720);
    float*         red = (float*)        (ds + 40960);
    __nv_bfloat16* Ph  = (__nv_bfloat16*)(ds + 43008);
    __nv_bfloat16* Pl  = (__nv_bfloat16*)(ds + 77824);
    __nv_bfloat16* Svh = (__nv_bfloat16*)(ds + 112640);
    __nv_bfloat16* Svl = (__nv_bfloat16*)(ds + 147456);

    const int bh = blockIdx.y;
    const int b = bh >> 5, h = bh & 31;
    const int kvh = h >> 2;
    const int bk = b * NKVh + kvh;
    const int m0 = blockIdx.x * 128;

    const float* __restrict__ Q  = g_q + (size_t)b * Ss * QD  + (size_t)h * HDd;
    const float* __restrict__ Kp = g_k + (size_t)b * Ss * KVD + (size_t)kvh * HDd;
    const __nv_bfloat16* __restrict__ Vh = g_vhi + (size_t)bk * HDd * Ss;
    const __nv_bfloat16* __restrict__ Vl = g_vlo + (size_t)bk * HDd * Ss;
    __nv_bfloat16* __restrict__ Ohi = g_ahi + (size_t)b * Ss * QD + (size_t)h * HDd;
    __nv_bfloat16* __restrict__ Olo = g_alo + (size_t)b * Ss * QD + (size_t)h * HDd;

    const int tid  = threadIdx.x;
    const int wid  = tid >> 5;
    const int lane = tid & 31;
    const int g    = lane >> 2;
    const int t    = lane & 3;
    const int wrow = (wid >> 2) * 64;
    const int wcol = (wid & 3) * 32;
    const int wc   = wid & 3;
    const float scale = 0.08838834764831845f;  // 1/sqrt(128)

    float oacc[4][4][4];
    float M[8], L[8];
#pragma unroll
    for (int i = 0; i < 4; i++)
#pragma unroll
        for (int j = 0; j < 4; j++)
#pragma unroll
            for (int r = 0; r < 4; r++) oacc[i][j][r] = 0.f;
#pragma unroll
    for (int i = 0; i < 8; i++) { M[i] = -INFINITY; L[i] = 0.f; }

    for (int n0 = 0; n0 <= m0; n0 += 128) {
        // ---------- QK: s = Q . K^T ----------
        float s[4][4][4];
#pragma unroll
        for (int i = 0; i < 4; i++)
#pragma unroll
            for (int j = 0; j < 4; j++)
#pragma unroll
                for (int r = 0; r < 4; r++) s[i][j][r] = 0.f;

        for (int kc = 0; kc < HDd; kc += 32) {
#pragma unroll
            for (int l = 0; l < 4; l++) {
                int seg = tid + l * 256;
                int row = seg >> 3;
                int c4  = (seg & 7) * 4;
                float4 va = *(const float4*)&Q[(size_t)(m0 + row) * QD + kc + c4];
                float hx = __bfloat162float(__float2bfloat16_rn(va.x));
                float hy = __bfloat162float(__float2bfloat16_rn(va.y));
                float hz = __bfloat162float(__float2bfloat16_rn(va.z));
                float hw = __bfloat162float(__float2bfloat16_rn(va.w));
                *(uint32_t*)&sqh[row * ST + c4]     = packbf(hx, hy);
                *(uint32_t*)&sqh[row * ST + c4 + 2] = packbf(hz, hw);
                *(uint32_t*)&sql[row * ST + c4]     = packbf(va.x - hx, va.y - hy);
                *(uint32_t*)&sql[row * ST + c4 + 2] = packbf(va.z - hz, va.w - hw);

                float4 vb = *(const float4*)&Kp[(size_t)(n0 + row) * KVD + kc + c4];
                float gx = __bfloat162float(__float2bfloat16_rn(vb.x));
                float gy = __bfloat162float(__float2bfloat16_rn(vb.y));
                float gz = __bfloat162float(__float2bfloat16_rn(vb.z));
                float gw = __bfloat162float(__float2bfloat16_rn(vb.w));
                *(uint32_t*)&skh[row * ST + c4]     = packbf(gx, gy);
                *(uint32_t*)&skh[row * ST + c4 + 2] = packbf(gz, gw);
                *(uint32_t*)&skl[row * ST + c4]     = packbf(vb.x - gx, vb.y - gy);
                *(uint32_t*)&skl[row * ST + c4 + 2] = packbf(vb.z - gz, vb.w - gw);
            }
            __syncthreads();
#pragma unroll
            for (int kk = 0; kk < 32; kk += 16) {
                uint32_t ah[4][4], al[4][4], bh2[4][2], bl2[4][2];
#pragma unroll
                for (int mt = 0; mt < 4; mt++) {
                    int m = wrow + mt * 16 + g;
                    ah[mt][0] = *(const uint32_t*)&sqh[(m    ) * ST + kk + 2 * t    ];
                    ah[mt][1] = *(const uint32_t*)&sqh[(m + 8) * ST + kk + 2 * t    ];
                    ah[mt][2] = *(const uint32_t*)&sqh[(m    ) * ST + kk + 2 * t + 8];
                    ah[mt][3] = *(const uint32_t*)&sqh[(m + 8) * ST + kk + 2 * t + 8];
                    al[mt][0] = *(const uint32_t*)&sql[(m    ) * ST + kk + 2 * t    ];
                    al[mt][1] = *(const uint32_t*)&sql[(m + 8) * ST + kk + 2 * t    ];
                    al[mt][2] = *(const uint32_t*)&sql[(m    ) * ST + kk + 2 * t + 8];
                    al[mt][3] = *(const uint32_t*)&sql[(m + 8) * ST + kk + 2 * t + 8];
                }
#pragma unroll
                for (int nt = 0; nt < 4; nt++) {
                    int n = wcol + nt * 8 + g;
                    bh2[nt][0] = *(const uint32_t*)&skh[n * ST + kk + 2 * t    ];
                    bh2[nt][1] = *(const uint32_t*)&skh[n * ST + kk + 2 * t + 8];
                    bl2[nt][0] = *(const uint32_t*)&skl[n * ST + kk + 2 * t    ];
                    bl2[nt][1] = *(const uint32_t*)&skl[n * ST + kk + 2 * t + 8];
                }
#pragma unroll
                for (int mt = 0; mt < 4; mt++)
#pragma unroll
                    for (int nt = 0; nt < 4; nt++) {
                        mma16816(s[mt][nt], ah[mt], bh2[nt]);
                        mma16816(s[mt][nt], al[mt], bh2[nt]);
                        mma16816(s[mt][nt], ah[mt], bl2[nt]);
                    }
            }
            __syncthreads();
        }

        // ---------- load V^T tile (hi/lo) ----------
#pragma unroll
        for (int l = 0; l < 8; l++) {
            int seg = tid + l * 256;
            int row = seg >> 4;
            int cs  = (seg & 15) * 8;
            *(uint4*)&Svh[row * PST + cs] = *(const uint4*)&Vh[(size_t)row * Ss + n0 + cs];
            *(uint4*)&Svl[row * PST + cs] = *(const uint4*)&Vl[(size_t)row * Ss + n0 + cs];
        }

        // ---------- scale + causal mask + tile row-max ----------
        float tstat[8];
#pragma unroll
        for (int mt = 0; mt < 4; mt++) {
#pragma unroll
            for (int half = 0; half < 2; half++) {
                int rl = wrow + mt * 16 + g + half * 8;
                float mx = -INFINITY;
#pragma unroll
                for (int nt = 0; nt < 4; nt++) {
#pragma unroll
                    for (int j = 0; j < 2; j++) {
                        int cl = wcol + nt * 8 + 2 * t + j;
                        float sv = s[mt][nt][half * 2 + j] * scale;
                        bool ok = (n0 + cl) <= (m0 + rl);
                        sv = ok ? sv : -INFINITY;
                        s[mt][nt][half * 2 + j] = sv;
                        mx = fmaxf(mx, sv);
                    }
                }
                mx = fmaxf(mx, __shfl_xor_sync(0xffffffffu, mx, 1));
                mx = fmaxf(mx, __shfl_xor_sync(0xffffffffu, mx, 2));
                tstat[mt * 2 + half] = mx;
            }
        }
        if (t == 0) {
#pragma unroll
            for (int mt = 0; mt < 4; mt++)
#pragma unroll
                for (int half = 0; half < 2; half++) {
                    int rl = wrow + mt * 16 + g + half * 8;
                    red[rl * 4 + wc] = tstat[mt * 2 + half];
                }
        }
        __syncthreads();

        float Mn[8], alpha[8];
#pragma unroll
        for (int mt = 0; mt < 4; mt++) {
#pragma unroll
            for (int half = 0; half < 2; half++) {
                int i = mt * 2 + half;
                int rl = wrow + mt * 16 + g + half * 8;
                float tm = fmaxf(fmaxf(red[rl * 4 + 0], red[rl * 4 + 1]),
                                 fmaxf(red[rl * 4 + 2], red[rl * 4 + 3]));
                Mn[i] = fmaxf(M[i], tm);
                alpha[i] = expf(M[i] - Mn[i]);
                M[i] = Mn[i];
            }
        }
        __syncthreads();   // red reused for sums

        // ---------- p = exp(s - M), write P hi/lo to smem, row sums ----------
#pragma unroll
        for (int mt = 0; mt < 4; mt++) {
#pragma unroll
            for (int half = 0; half < 2; half++) {
                int i = mt * 2 + half;
                int rl = wrow + mt * 16 + g + half * 8;
                float sm = 0.f;
#pragma unroll
                for (int nt = 0; nt < 4; nt++) {
                    float pa = expf(s[mt][nt][half * 2 + 0] - M[i]);
                    float pb = expf(s[mt][nt][half * 2 + 1] - M[i]);
                    sm += pa + pb;
                    float ha = __bfloat162float(__float2bfloat16_rn(pa));
                    float hb = __bfloat162float(__float2bfloat16_rn(pb));
                    int cl = wcol + nt * 8 + 2 * t;
                    *(uint32_t*)&Ph[rl * PST + cl] = packbf(ha, hb);
                    *(uint32_t*)&Pl[rl * PST + cl] = packbf(pa - ha, pb - hb);
                }
                sm += __shfl_xor_sync(0xffffffffu, sm, 1);
                sm += __shfl_xor_sync(0xffffffffu, sm, 2);
                tstat[i] = sm;
            }
        }
        if (t == 0) {
#pragma unroll
            for (int mt = 0; mt < 4; mt++)
#pragma unroll
                for (int half = 0; half < 2; half++) {
                    int rl = wrow + mt * 16 + g + half * 8;
                    red[rl * 4 + wc] = tstat[mt * 2 + half];
                }
        }
        __syncthreads();

#pragma unroll
        for (int mt = 0; mt < 4; mt++) {
#pragma unroll
            for (int half = 0; half < 2; half++) {
                int i = mt * 2 + half;
                int rl = wrow + mt * 16 + g + half * 8;
                float rs = red[rl * 4 + 0] + red[rl * 4 + 1] +
                           red[rl * 4 + 2] + red[rl * 4 + 3];
                L[i] = L[i] * alpha[i] + rs;
            }
        }
#pragma unroll
        for (int mt = 0; mt < 4; mt++)
#pragma unroll
            for (int nt = 0; nt < 4; nt++) {
                oacc[mt][nt][0] *= alpha[mt * 2 + 0];
                oacc[mt][nt][1] *= alpha[mt * 2 + 0];
                oacc[mt][nt][2] *= alpha[mt * 2 + 1];
                oacc[mt][nt][3] *= alpha[mt * 2 + 1];
            }

        // ---------- PV: O += P . V^T ----------
#pragma unroll
        for (int kk = 0; kk < 128; kk += 16) {
            uint32_t ah[4][4], al[4][4], bh2[4][2], bl2[4][2];
#pragma unroll
            for (int mt = 0; mt < 4; mt++) {
                int m = wrow + mt * 16 + g;
                ah[mt][0] = *(const uint32_t*)&Ph[(m    ) * PST + kk + 2 * t    ];
                ah[mt][1] = *(const uint32_t*)&Ph[(m + 8) * PST + kk + 2 * t    ];
                ah[mt][2] = *(const uint32_t*)&Ph[(m    ) * PST + kk + 2 * t + 8];
                ah[mt][3] = *(const uint32_t*)&Ph[(m + 8) * PST + kk + 2 * t + 8];
                al[mt][0] = *(const uint32_t*)&Pl[(m    ) * PST + kk + 2 * t    ];
                al[mt][1] = *(const uint32_t*)&Pl[(m + 8) * PST + kk + 2 * t    ];
                al[mt][2] = *(const uint32_t*)&Pl[(m    ) * PST + kk + 2 * t + 8];
                al[mt][3] = *(const uint32_t*)&Pl[(m + 8) * PST + kk + 2 * t + 8];
            }
#pragma unroll
            for (int nt = 0; nt < 4; nt++) {
                int n = wcol + nt * 8 + g;
                bh2[nt][0] = *(const uint32_t*)&Svh[n * PST + kk + 2 * t    ];
                bh2[nt][1] = *(const uint32_t*)&Svh[n * PST + kk + 2 * t + 8];
                bl2[nt][0] = *(const uint32_t*)&Svl[n * PST + kk + 2 * t    ];
                bl2[nt][1] = *(const uint32_t*)&Svl[n * PST + kk + 2 * t + 8];
            }
#pragma unroll
            for (int mt = 0; mt < 4; mt++)
#pragma unroll
                for (int nt = 0; nt < 4; nt++) {
                    mma16816(oacc[mt][nt], ah[mt], bh2[nt]);
                    mma16816(oacc[mt][nt], al[mt], bh2[nt]);
                    mma16816(oacc[mt][nt], ah[mt], bl2[nt]);
                }
        }
        __syncthreads();
    }

    // ---------- epilogue: O /= L, write hi/lo bf16 planes ----------
    float inv[8];
#pragma unroll
    for (int i = 0; i < 8; i++) inv[i] = 1.f / L[i];
#pragma unroll
    for (int mt = 0; mt < 4; mt++) {
#pragma unroll
        for (int nt = 0; nt < 4; nt++) {
            int m = m0 + wrow + mt * 16 + g;
            int n = wcol + nt * 8 + 2 * t;
            float v0 = oacc[mt][nt][0] * inv[mt * 2 + 0];
            float v1 = oacc[mt][nt][1] * inv[mt * 2 + 0];
            float h0 = __bfloat162float(__float2bfloat16_rn(v0));
            float h1 = __bfloat162float(__float2bfloat16_rn(v1));
            *(uint32_t*)&Ohi[(size_t)m * QD + n] = packbf(h0, h1);
            *(uint32_t*)&Olo[(size_t)m * QD + n] = packbf(v0 - h0, v1 - h1);

            float v2 = oacc[mt][nt][2] * inv[mt * 2 + 1];
            float v3 = oacc[mt][nt][3] * inv[mt * 2 + 1];
            float h2 = __bfloat162float(__float2bfloat16_rn(v2));
            float h3 = __bfloat162float(__float2bfloat16_rn(v3));
            *(uint32_t*)&Ohi[(size_t)(m + 8) * QD + n] = packbf(h2, h3);
            *(uint32_t*)&Olo[(size_t)(m + 8) * QD + n] = packbf(v2 - h2, v3 - h3);
        }
    }
}

// ---------------- launch ----------------
extern "C" void kernel_launch(void* const* d_in, const int* in_sizes, int n_in,
                              void* d_out, int out_size)
{
    const float* hidden = nullptr;
    const float* big16[2] = {nullptr, nullptr};
    const float* sml4[2]  = {nullptr, nullptr};
    const int*   posid = nullptr;
    int hidden_idx = -1, nb = 0, ns = 0;
    for (int i = 0; i < n_in; i++) {
        if (in_sizes[i] == 8388608)               { hidden = (const float*)d_in[i]; hidden_idx = i; }
        else if (in_sizes[i] == 16777216 && nb<2) { big16[nb++] = (const float*)d_in[i]; }
        else if (in_sizes[i] == 4194304  && ns<2) { sml4[ns++]  = (const float*)d_in[i]; }
        else if (in_sizes[i] == 2048)             { posid = (const int*)d_in[i]; }
    }
    const float* Wq = (hidden_idx == 0) ? big16[0] : big16[1];
    const float* Wo = (hidden_idx == 0) ? big16[1] : big16[0];
    const float* Wk = sml4[0];
    const float* Wv = sml4[1];
    float* out = (float*)d_out;

    void *pq, *pk, *pv, *pahi, *palo, *pwq, *pwk, *pwv, *pwo;
    cudaGetSymbolAddress(&pq, g_q);
    cudaGetSymbolAddress(&pk, g_k);
    cudaGetSymbolAddress(&pv, g_v);
    cudaGetSymbolAddress(&pahi, g_ahi);
    cudaGetSymbolAddress(&palo, g_alo);
    cudaGetSymbolAddress(&pwq, g_wq);
    cudaGetSymbolAddress(&pwk, g_wk);
    cudaGetSymbolAddress(&pwv, g_wv);
    cudaGetSymbolAddress(&pwo, g_wo);

    cudaFuncSetAttribute(gemm_mma2, cudaFuncAttributeMaxDynamicSharedMemorySize, GM_SMEM);
    cudaFuncSetAttribute(flash_mma, cudaFuncAttributeMaxDynamicSharedMemorySize, FL_SMEM);

    const size_t nQ4 = (size_t)QD * Hh / 4;
    const size_t nK4 = (size_t)KVD * Hh / 4;
    const size_t nO4 = (size_t)Hh * QD / 4;
    const size_t nH4 = (size_t)MTOK * Hh / 4;

    // Streams/events created once (pre-capture correctness call) so graph
    // capture performs no driver allocations.
    static cudaStream_t s2 = nullptr;
    static cudaEvent_t ev0, evQw, evK, evV, evO, evSp, evVgemm, evKg, evVS;
    if (s2 == nullptr) {
        cudaStreamCreateWithFlags(&s2, cudaStreamNonBlocking);
        cudaEventCreateWithFlags(&ev0, cudaEventDisableTiming);
        cudaEventCreateWithFlags(&evQw, cudaEventDisableTiming);
        cudaEventCreateWithFlags(&evK, cudaEventDisableTiming);
        cudaEventCreateWithFlags(&evV, cudaEventDisableTiming);
        cudaEventCreateWithFlags(&evO, cudaEventDisableTiming);
        cudaEventCreateWithFlags(&evSp, cudaEventDisableTiming);
        cudaEventCreateWithFlags(&evVgemm, cudaEventDisableTiming);
        cudaEventCreateWithFlags(&evKg, cudaEventDisableTiming);
        cudaEventCreateWithFlags(&evVS, cudaEventDisableTiming);
    }

    init_kernel<<<1, 32>>>();
    cudaEventRecord(ev0, 0);
    cudaStreamWaitEvent(s2, ev0, 0);

    // side stream: Wq/Wk/Wv preprocessing (O's moved after V gemm — ample slack)
    abssum_kernel<<<2048, 256, 0, s2>>>((const float4*)Wq, nQ4, 0);
    quantize_kernel<<<4096, 256, 0, s2>>>((const float4*)Wq, (__nv_bfloat162*)pwq, nQ4, 0);
    cudaEventRecord(evQw, s2);
    abssum_kernel<<<2048, 256, 0, s2>>>((const float4*)Wk, nK4, 1);
    quantize_kernel<<<4096, 256, 0, s2>>>((const float4*)Wk, (__nv_bfloat162*)pwk, nK4, 1);
    cudaEventRecord(evK, s2);
    abssum_kernel<<<2048, 256, 0, s2>>>((const float4*)Wv, nK4, 2);
    quantize_kernel<<<4096, 256, 0, s2>>>((const float4*)Wv, (__nv_bfloat162*)pwv, nK4, 2);
    cudaEventRecord(evV, s2);

    // main stream: activation split (concurrent with Wq preprocessing)
    split2_kernel<<<4096, 256>>>((const float4*)hidden, (__nv_bfloat162*)pahi,
                                 (__nv_bfloat162*)palo, nH4);
    cudaEventRecord(evSp, 0);

    // main: Q projection
    cudaStreamWaitEvent(0, evQw, 0);
    gemm_mma2<<<dim3(QD / 128, MTOK / 128), 256, GM_SMEM>>>(
        (const __nv_bfloat16*)pahi, (const __nv_bfloat16*)palo,
        (const __nv_bfloat16*)pwq, (float*)pq, QD, Hh, 0);

    // side stream: V projection runs CONCURRENTLY with Q/K projections
    cudaStreamWaitEvent(s2, evSp, 0);   // (evV already ordered on s2)
    gemm_mma2<<<dim3(KVD / 128, MTOK / 128), 256, GM_SMEM, s2>>>(
        (const __nv_bfloat16*)pahi, (const __nv_bfloat16*)palo,
        (const __nv_bfloat16*)pwv, (float*)pv, KVD, Hh, 2);
    cudaEventRecord(evVgemm, s2);
    // side stream: V transpose/split immediately after V projection
    vsplit_kernel<<<(int)(((size_t)Bb * NKVh * HDd * Ss + 255) / 256), 256, 0, s2>>>();
    cudaEventRecord(evVS, s2);
    // side stream: Wo preprocessing (needed only before the final GEMM)
    abssum_kernel<<<2048, 256, 0, s2>>>((const float4*)Wo, nO4, 3);
    quantize_kernel<<<4096, 256, 0, s2>>>((const float4*)Wo, (__nv_bfloat162*)pwo, nO4, 3);
    cudaEventRecord(evO, s2);

    // main: K projection
    cudaStreamWaitEvent(0, evK, 0);
    gemm_mma2<<<dim3(KVD / 128, MTOK / 128), 256, GM_SMEM>>>(
        (const __nv_bfloat16*)pahi, (const __nv_bfloat16*)palo,
        (const __nv_bfloat16*)pwk, (float*)pk, KVD, Hh, 1);

    // main: RoPE (Q and K in place)
    rope_kernel<<<(int)(((size_t)MTOK * NHq * 64 + 255) / 256), 256>>>((float*)pq, NHq, posid);
    rope_kernel<<<(int)(((size_t)MTOK * NKVh * 64 + 255) / 256), 256>>>((float*)pk, NKVh, posid);

    // main: fused attention (needs vsplit from s2)
    cudaStreamWaitEvent(0, evVS, 0);
    flash_mma<<<dim3(Ss / 128, Bb * NHq), 256, FL_SMEM>>>();

    // main: output projection
    cudaStreamWaitEvent(0, evO, 0);
    gemm_mma2<<<dim3(Hh / 128, MTOK / 128), 256, GM_SMEM>>>(
        (const __nv_bfloat16*)pahi, (const __nv_bfloat16*)palo,
        (const __nv_bfloat16*)pwo, out, Hh, QD, 3);
}